// round 9
// baseline (speedup 1.0000x reference)
#include <cuda_runtime.h>
#include <cuda_bf16.h>
#include <math.h>

#define SQ   2048
#define DIM  1024
#define NH   16
#define HD   64
#define FACT 16

// ---- scratch (device globals: the sanctioned no-alloc scratch path) ----
__device__ float g_V[NH * SQ * HD];              // 8 MB fp32 [h][s][hd]
__device__ float g_scores[(size_t)NH * SQ * SQ]; // 256 MB [h][q][k]
__device__ float g_vsum[NH * HD];
__device__ float g_attn[SQ * DIM];               // 8 MB fp32 [s][d]

// bf16 split planes
__device__ __nv_bfloat16 g_xh[SQ * DIM],  g_xl[SQ * DIM];        // 4 MB each
__device__ __nv_bfloat16 g_ath[SQ * DIM], g_atl[SQ * DIM];       // 4 MB each
__device__ __nv_bfloat16 g_WTh[4 * DIM * DIM], g_WTl[4 * DIM * DIM]; // 8 MB each
__device__ __nv_bfloat16 g_Qh[NH * SQ * HD], g_Ql[NH * SQ * HD]; // 4 MB each
__device__ __nv_bfloat16 g_Kh[NH * SQ * HD], g_Kl[NH * SQ * HD]; // 4 MB each

// ============================================================
// helpers
// ============================================================
__device__ __forceinline__ void bsplit(float v, __nv_bfloat16& h, __nv_bfloat16& l) {
    h = __float2bfloat16(v);
    l = __float2bfloat16(v - __bfloat162float(h));
}

__device__ __forceinline__ void mma_bf16(float* c, const unsigned* a, const unsigned* b) {
    asm volatile(
        "mma.sync.aligned.m16n8k16.row.col.f32.bf16.bf16.f32 "
        "{%0,%1,%2,%3}, {%4,%5,%6,%7}, {%8,%9}, {%0,%1,%2,%3};"
        : "+f"(c[0]), "+f"(c[1]), "+f"(c[2]), "+f"(c[3])
        : "r"(a[0]), "r"(a[1]), "r"(a[2]), "r"(a[3]),
          "r"(b[0]), "r"(b[1]));
}

// ============================================================
// 1024x1024 transpose + bf16 hi/lo split (weights -> NT planes)
// ============================================================
__global__ __launch_bounds__(256) void transpose_split(
    const float* __restrict__ S,
    __nv_bfloat16* __restrict__ Dh, __nv_bfloat16* __restrict__ Dl)
{
    __shared__ float tile[32][33];
    int x = blockIdx.x * 32 + threadIdx.x;
    int y = blockIdx.y * 32 + threadIdx.y;
#pragma unroll
    for (int j = 0; j < 32; j += 8)
        tile[threadIdx.y + j][threadIdx.x] = S[(size_t)(y + j) * DIM + x];
    __syncthreads();
    x = blockIdx.y * 32 + threadIdx.x;
    y = blockIdx.x * 32 + threadIdx.y;
#pragma unroll
    for (int j = 0; j < 32; j += 8) {
        float v = tile[threadIdx.x][threadIdx.y + j];
        __nv_bfloat16 h, l;
        bsplit(v, h, l);
        Dh[(size_t)(y + j) * DIM + x] = h;
        Dl[(size_t)(y + j) * DIM + x] = l;
    }
}

// ============================================================
// elementwise fp32 -> bf16 hi/lo split
// ============================================================
__global__ __launch_bounds__(256) void split_convert(
    const float* __restrict__ S,
    __nv_bfloat16* __restrict__ Dh, __nv_bfloat16* __restrict__ Dl, int n4)
{
    int i = blockIdx.x * 256 + threadIdx.x;
    if (i >= n4) return;
    float4 v = *(const float4*)&S[i * 4];
    __nv_bfloat16 h0,h1,h2,h3,l0,l1,l2,l3;
    bsplit(v.x, h0, l0); bsplit(v.y, h1, l1);
    bsplit(v.z, h2, l2); bsplit(v.w, h3, l3);
    __nv_bfloat162* ph = (__nv_bfloat162*)&Dh[i * 4];
    __nv_bfloat162* pl = (__nv_bfloat162*)&Dl[i * 4];
    ph[0] = __nv_bfloat162(h0, h1); ph[1] = __nv_bfloat162(h2, h3);
    pl[0] = __nv_bfloat162(l0, l1); pl[1] = __nv_bfloat162(l2, l3);
}

// ============================================================
// NT bf16x3 tensor-core GEMM (fp32-accurate):
//   C[m][n] = alpha * sum_k A[m][k]*B[n][k]  (+ bias[n])
// Operands pre-split into bf16 hi/lo planes in gmem.
// 128x128 tile, BK=64, 8 warps of 64x32 (m16n8k16), cp.async
// double-buffered. mode: 0=fp32 C[row*ldc+col]; 1=fp32 remap to
// [h][row][t]; 2=bf16 split remap to Ch/Cl [h][row][t].
// blockIdx.z batches via strA/strB/strC (elements).
// ============================================================
#define BK   64
#define SWW  36                 // word (2xbf16) stride per row
#define PLANE_W (128 * SWW)     // words per plane
#define GSMEM_BYTES (2 * 4 * PLANE_W * 4)   // 147456

__global__ __launch_bounds__(256) void nt_bf16x3_gemm(
    const __nv_bfloat16* __restrict__ Ah, const __nv_bfloat16* __restrict__ Al,
    const __nv_bfloat16* __restrict__ Bh, const __nv_bfloat16* __restrict__ Bl,
    const float* __restrict__ bias, float* __restrict__ C,
    __nv_bfloat16* __restrict__ Ch, __nv_bfloat16* __restrict__ Cl,
    int K, int lda, int ldb, int ldc,
    float alpha, int mode,
    long strA, long strB, long strC)
{
    extern __shared__ unsigned sm[];
    unsigned sbase = (unsigned)__cvta_generic_to_shared(sm);

    Ah += (size_t)blockIdx.z * strA;  Al += (size_t)blockIdx.z * strA;
    Bh += (size_t)blockIdx.z * strB;  Bl += (size_t)blockIdx.z * strB;

    const int tid  = threadIdx.x;
    const int lane = tid & 31;
    const int wid  = tid >> 5;
    const int wm   = (wid >> 2) * 64;
    const int wn   = (wid & 3) * 32;
    const int g    = lane >> 2;
    const int t    = lane & 3;

    const int m0 = blockIdx.y * 128;
    const int n0 = blockIdx.x * 128;

    const __nv_bfloat16* gp0 = Ah + (size_t)m0 * lda;
    const __nv_bfloat16* gp1 = Al + (size_t)m0 * lda;
    const __nv_bfloat16* gp2 = Bh + (size_t)n0 * ldb;
    const __nv_bfloat16* gp3 = Bl + (size_t)n0 * ldb;

    float acc[4][4][4];
#pragma unroll
    for (int mt = 0; mt < 4; mt++)
#pragma unroll
        for (int nt = 0; nt < 4; nt++)
#pragma unroll
            for (int e = 0; e < 4; e++) acc[mt][nt][e] = 0.0f;

    const int T = K / BK;

    // ---- staging lambda-ish macro: tile -> buffer buf at k-offset k0 ----
#define STAGE(BUF, K0)                                                        \
    do {                                                                      \
        const __nv_bfloat16* gps[4] = {gp0, gp1, gp2, gp3};                   \
        _Pragma("unroll")                                                     \
        for (int p = 0; p < 4; p++) {                                         \
            const int ld = (p < 2) ? lda : ldb;                               \
            const unsigned sb = sbase + ((BUF) * 4 + p) * (PLANE_W * 4);      \
            _Pragma("unroll")                                                 \
            for (int i = 0; i < 4; i++) {                                     \
                const int c   = tid + i * 256;                                \
                const int row = c >> 3;                                       \
                const int c8  = c & 7;                                        \
                const __nv_bfloat16* src = gps[p] + (size_t)row * ld + (K0) + c8 * 8; \
                const unsigned dst = sb + row * (SWW * 4) + c8 * 16;          \
                asm volatile("cp.async.cg.shared.global [%0], [%1], 16;"      \
                             :: "r"(dst), "l"(src));                          \
            }                                                                 \
        }                                                                     \
        asm volatile("cp.async.commit_group;");                               \
    } while (0)

    STAGE(0, 0);

    for (int tt = 0; tt < T; tt++) {
        if (tt + 1 < T) {
            STAGE((tt + 1) & 1, (tt + 1) * BK);
            asm volatile("cp.async.wait_group 1;");
        } else {
            asm volatile("cp.async.wait_group 0;");
        }
        __syncthreads();

        const unsigned* AH = sm + ((tt & 1) * 4 + 0) * PLANE_W;
        const unsigned* AL = sm + ((tt & 1) * 4 + 1) * PLANE_W;
        const unsigned* BH = sm + ((tt & 1) * 4 + 2) * PLANE_W;
        const unsigned* BL = sm + ((tt & 1) * 4 + 3) * PLANE_W;

#pragma unroll
        for (int ks = 0; ks < 4; ks++) {
            unsigned ah[4][4], al[4][4], bh[4][2], bl[4][2];
#pragma unroll
            for (int mt = 0; mt < 4; mt++) {
                const int w0 = (wm + mt * 16 + g) * SWW + ks * 8 + t;
                const int w1 = w0 + 8 * SWW;
                ah[mt][0] = AH[w0]; ah[mt][1] = AH[w1];
                ah[mt][2] = AH[w0 + 4]; ah[mt][3] = AH[w1 + 4];
                al[mt][0] = AL[w0]; al[mt][1] = AL[w1];
                al[mt][2] = AL[w0 + 4]; al[mt][3] = AL[w1 + 4];
            }
#pragma unroll
            for (int nt = 0; nt < 4; nt++) {
                const int wb = (wn + nt * 8 + g) * SWW + ks * 8 + t;
                bh[nt][0] = BH[wb]; bh[nt][1] = BH[wb + 4];
                bl[nt][0] = BL[wb]; bl[nt][1] = BL[wb + 4];
            }
#pragma unroll
            for (int mt = 0; mt < 4; mt++)
#pragma unroll
                for (int nt = 0; nt < 4; nt++) {
                    mma_bf16(acc[mt][nt], al[mt], bh[nt]);
                    mma_bf16(acc[mt][nt], ah[mt], bl[nt]);
                    mma_bf16(acc[mt][nt], ah[mt], bh[nt]);
                }
        }
        __syncthreads();
    }

    // ---- epilogue ----
#pragma unroll
    for (int mt = 0; mt < 4; mt++) {
        const int rowA = m0 + wm + mt * 16 + g;
        const int rowB = rowA + 8;
#pragma unroll
        for (int nt = 0; nt < 4; nt++) {
            const int col = n0 + wn + nt * 8 + 2 * t;
            float bx = 0.0f, by = 0.0f;
            if (bias) { bx = bias[col]; by = bias[col + 1]; }
            float lox = acc[mt][nt][0] * alpha + bx;
            float loy = acc[mt][nt][1] * alpha + by;
            float hix = acc[mt][nt][2] * alpha + bx;
            float hiy = acc[mt][nt][3] * alpha + by;
            if (mode == 0) {
                float* Cz = C + (size_t)blockIdx.z * strC;
                *(float2*)&Cz[(size_t)rowA * ldc + col] = make_float2(lox, loy);
                *(float2*)&Cz[(size_t)rowB * ldc + col] = make_float2(hix, hiy);
            } else if (mode == 1) {
                const int h = col >> 6, tc = col & 63;
                *(float2*)&C[((size_t)h * SQ + rowA) * HD + tc] = make_float2(lox, loy);
                *(float2*)&C[((size_t)h * SQ + rowB) * HD + tc] = make_float2(hix, hiy);
            } else {
                const int h = col >> 6, tc = col & 63;
                __nv_bfloat16 h0,h1,h2,h3,l0,l1,l2,l3;
                bsplit(lox, h0, l0); bsplit(loy, h1, l1);
                bsplit(hix, h2, l2); bsplit(hiy, h3, l3);
                *(__nv_bfloat162*)&Ch[((size_t)h * SQ + rowA) * HD + tc] = __nv_bfloat162(h0, h1);
                *(__nv_bfloat162*)&Cl[((size_t)h * SQ + rowA) * HD + tc] = __nv_bfloat162(l0, l1);
                *(__nv_bfloat162*)&Ch[((size_t)h * SQ + rowB) * HD + tc] = __nv_bfloat162(h2, h3);
                *(__nv_bfloat162*)&Cl[((size_t)h * SQ + rowB) * HD + tc] = __nv_bfloat162(l2, l3);
            }
        }
    }
#undef STAGE
}

// ============================================================
// Per-head V column sums
// ============================================================
__global__ __launch_bounds__(256) void vsum_kernel()
{
    const int h = blockIdx.x;
    const int t = threadIdx.x & 63;
    const int g = threadIdx.x >> 6;
    const float* Vh = g_V + (size_t)h * SQ * HD;
    float s = 0.0f;
    for (int r = g * 512; r < (g + 1) * 512; ++r)
        s += Vh[(size_t)r * HD + t];
    __shared__ float red[4][64];
    red[g][t] = s;
    __syncthreads();
    if (g == 0)
        g_vsum[h * HD + t] = red[0][t] + red[1][t] + red[2][t] + red[3][t];
}

// ============================================================
// Top-16 + sparse softmax + PV gather. One warp per (h, q).
// (unchanged from the 966us kernel)
// ============================================================
__global__ __launch_bounds__(128) void topk_attend()
{
    const unsigned FULL = 0xffffffffu;
    const int gwarp = (blockIdx.x * 128 + threadIdx.x) >> 5;
    const int lane  = threadIdx.x & 31;
    const int h = gwarp >> 11;
    const int q = gwarp & 2047;

    const float* row = g_scores + ((size_t)h * SQ + q) * SQ;

    float lv[16];
    int   li[16];
#pragma unroll
    for (int i = 0; i < 16; i++) { lv[i] = -1e30f; li[i] = 0; }

#pragma unroll 4
    for (int c = 0; c < 16; c++) {
        const int base = c * 128 + lane * 4;
        float4 v4 = *(const float4*)&row[base];
        float vals[4] = {v4.x, v4.y, v4.z, v4.w};
#pragma unroll
        for (int j = 0; j < 4; j++) {
            const float val = vals[j];
            if (val > lv[15]) {
                lv[15] = val; li[15] = base + j;
#pragma unroll
                for (int p = 15; p >= 1; --p) {
                    if (lv[p] > lv[p - 1]) {
                        float tv = lv[p]; lv[p] = lv[p - 1]; lv[p - 1] = tv;
                        int   ti = li[p]; li[p] = li[p - 1]; li[p - 1] = ti;
                    }
                }
            }
        }
    }

    float fv = -1e30f;
    int   fi = 0;
    for (int r = 0; r < 16; r++) {
        float bv = lv[0]; int bi = li[0]; int bl = lane;
#pragma unroll
        for (int off = 16; off > 0; off >>= 1) {
            float ov = __shfl_down_sync(FULL, bv, off);
            int   oi = __shfl_down_sync(FULL, bi, off);
            int   ol = __shfl_down_sync(FULL, bl, off);
            if (ov > bv) { bv = ov; bi = oi; bl = ol; }
        }
        bv = __shfl_sync(FULL, bv, 0);
        bi = __shfl_sync(FULL, bi, 0);
        bl = __shfl_sync(FULL, bl, 0);
        if (lane == bl) {
#pragma unroll
            for (int p = 0; p < 15; p++) { lv[p] = lv[p + 1]; li[p] = li[p + 1]; }
            lv[15] = -1e30f;
        }
        if (lane == r) { fv = bv; fi = bi; }
    }

    float m = __shfl_sync(FULL, fv, 0);
    m = fmaxf(m, 0.0f);
    float e = (lane < 16) ? expf(fv - m) : 0.0f;
    float z = e;
#pragma unroll
    for (int off = 16; off > 0; off >>= 1)
        z += __shfl_xor_sync(FULL, z, off);
    const float e0 = expf(-m);
    const float Z  = z + (float)(SQ - FACT) * e0;
    const float p0 = e0 / Z;
    const float w  = e / Z - p0;

    const float* Vh = g_V + (size_t)h * SQ * HD;
    float acc0 = p0 * g_vsum[h * HD + lane];
    float acc1 = p0 * g_vsum[h * HD + lane + 32];
#pragma unroll
    for (int i = 0; i < 16; i++) {
        const float wi  = __shfl_sync(FULL, w,  i);
        const int   idx = __shfl_sync(FULL, fi, i);
        const float* vr = Vh + (size_t)idx * HD;
        acc0 = fmaf(wi, vr[lane],      acc0);
        acc1 = fmaf(wi, vr[lane + 32], acc1);
    }
    float* o = g_attn + (size_t)q * DIM + h * HD;
    o[lane]      = acc0;
    o[lane + 32] = acc1;
}

// ============================================================
extern "C" void kernel_launch(void* const* d_in, const int* in_sizes, int n_in,
                              void* d_out, int out_size)
{
    const float* x  = (const float*)d_in[0];
    const float* Wq = (const float*)d_in[1];
    const float* bq = (const float*)d_in[2];
    const float* Wk = (const float*)d_in[3];
    const float* bk = (const float*)d_in[4];
    const float* Wv = (const float*)d_in[5];
    const float* bv = (const float*)d_in[6];
    const float* Wo = (const float*)d_in[7];
    const float* bo = (const float*)d_in[8];
    float* out = (float*)d_out;

    float *Vp, *attnp, *scoresp;
    __nv_bfloat16 *xh, *xl, *ath, *atl, *WTh, *WTl, *Qh, *Ql, *Kh, *Kl;
    cudaGetSymbolAddress((void**)&Vp,      g_V);
    cudaGetSymbolAddress((void**)&attnp,   g_attn);
    cudaGetSymbolAddress((void**)&scoresp, g_scores);
    cudaGetSymbolAddress((void**)&xh,  g_xh);  cudaGetSymbolAddress((void**)&xl,  g_xl);
    cudaGetSymbolAddress((void**)&ath, g_ath); cudaGetSymbolAddress((void**)&atl, g_atl);
    cudaGetSymbolAddress((void**)&WTh, g_WTh); cudaGetSymbolAddress((void**)&WTl, g_WTl);
    cudaGetSymbolAddress((void**)&Qh,  g_Qh);  cudaGetSymbolAddress((void**)&Ql,  g_Ql);
    cudaGetSymbolAddress((void**)&Kh,  g_Kh);  cudaGetSymbolAddress((void**)&Kl,  g_Kl);

    static int smem_set = 0;
    if (!smem_set) {
        cudaFuncSetAttribute(nt_bf16x3_gemm,
                             cudaFuncAttributeMaxDynamicSharedMemorySize,
                             GSMEM_BYTES);
        smem_set = 1;
    }

    const size_t DD = (size_t)DIM * DIM;

    dim3 gT(DIM / 32, DIM / 32);
    dim3 bT(32, 8);
    transpose_split<<<gT, bT>>>(Wq, WTh,          WTl);
    transpose_split<<<gT, bT>>>(Wk, WTh + DD,     WTl + DD);
    transpose_split<<<gT, bT>>>(Wv, WTh + 2 * DD, WTl + 2 * DD);
    transpose_split<<<gT, bT>>>(Wo, WTh + 3 * DD, WTl + 3 * DD);

    split_convert<<<(SQ * DIM / 4 + 255) / 256, 256>>>(x, xh, xl, SQ * DIM / 4);

    dim3 gProj(DIM / 128, SQ / 128, 1);
    // Q projection -> bf16 split planes
    nt_bf16x3_gemm<<<gProj, 256, GSMEM_BYTES>>>(
        xh, xl, WTh, WTl, bq, nullptr, Qh, Ql,
        DIM, DIM, DIM, DIM, 1.0f, 2, 0, 0, 0);
    // K projection -> bf16 split planes
    nt_bf16x3_gemm<<<gProj, 256, GSMEM_BYTES>>>(
        xh, xl, WTh + DD, WTl + DD, bk, nullptr, Kh, Kl,
        DIM, DIM, DIM, DIM, 1.0f, 2, 0, 0, 0);
    // V projection -> fp32 remap
    nt_bf16x3_gemm<<<gProj, 256, GSMEM_BYTES>>>(
        xh, xl, WTh + 2 * DD, WTl + 2 * DD, bv, Vp, nullptr, nullptr,
        DIM, DIM, DIM, DIM, 1.0f, 1, 0, 0, 0);

    vsum_kernel<<<NH, 256>>>();

    // scores: per-head NT GEMM over bf16 planes
    dim3 gSc(SQ / 128, SQ / 128, NH);
    nt_bf16x3_gemm<<<gSc, 256, GSMEM_BYTES>>>(
        Qh, Ql, Kh, Kl, nullptr, scoresp, nullptr, nullptr,
        HD, HD, HD, SQ, 0.125f, 0,
        (long)SQ * HD, (long)SQ * HD, (long)SQ * SQ);

    topk_attend<<<(NH * SQ) / 4, 128>>>();

    split_convert<<<(SQ * DIM / 4 + 255) / 256, 256>>>(attnp, ath, atl, SQ * DIM / 4);

    // output projection -> fp32 out
    nt_bf16x3_gemm<<<gProj, 256, GSMEM_BYTES>>>(
        ath, atl, WTh + 3 * DD, WTl + 3 * DD, bo, out, nullptr, nullptr,
        DIM, DIM, DIM, DIM, 1.0f, 0, 0, 0, 0);
}

// round 10
// speedup vs baseline: 1.0424x; 1.0424x over previous
#include <cuda_runtime.h>
#include <cuda_bf16.h>
#include <math.h>

#define SQ   2048
#define DIM  1024
#define NH   16
#define HD   64
#define FACT 16

// ---- scratch (device globals: the sanctioned no-alloc scratch path) ----
__device__ float g_V[NH * SQ * HD];              // 8 MB fp32 [h][s][hd]
__device__ float g_scores[(size_t)NH * SQ * SQ]; // 256 MB [h][q][k]
__device__ float g_vsum[NH * HD];
__device__ float g_attn[SQ * DIM];               // 8 MB fp32 [s][d]

// bf16 split planes
__device__ __nv_bfloat16 g_xh[SQ * DIM],  g_xl[SQ * DIM];
__device__ __nv_bfloat16 g_ath[SQ * DIM], g_atl[SQ * DIM];
__device__ __nv_bfloat16 g_WTh[4 * DIM * DIM], g_WTl[4 * DIM * DIM];
__device__ __nv_bfloat16 g_Qh[NH * SQ * HD], g_Ql[NH * SQ * HD];
__device__ __nv_bfloat16 g_Kh[NH * SQ * HD], g_Kl[NH * SQ * HD];

// ============================================================
// helpers
// ============================================================
__device__ __forceinline__ void bsplit(float v, __nv_bfloat16& h, __nv_bfloat16& l) {
    h = __float2bfloat16(v);
    l = __float2bfloat16(v - __bfloat162float(h));
}

__device__ __forceinline__ void mma_bf16(float* c, const unsigned* a, const unsigned* b) {
    asm volatile(
        "mma.sync.aligned.m16n8k16.row.col.f32.bf16.bf16.f32 "
        "{%0,%1,%2,%3}, {%4,%5,%6,%7}, {%8,%9}, {%0,%1,%2,%3};"
        : "+f"(c[0]), "+f"(c[1]), "+f"(c[2]), "+f"(c[3])
        : "r"(a[0]), "r"(a[1]), "r"(a[2]), "r"(a[3]),
          "r"(b[0]), "r"(b[1]));
}

#define LDSM4(R0, R1, R2, R3, A)                                          \
    asm volatile("ldmatrix.sync.aligned.m8n8.x4.shared.b16 "              \
                 "{%0,%1,%2,%3}, [%4];"                                   \
                 : "=r"(R0), "=r"(R1), "=r"(R2), "=r"(R3) : "r"(A))

// ============================================================
// 1024x1024 transpose + bf16 hi/lo split (weights -> NT planes)
// ============================================================
__global__ __launch_bounds__(256) void transpose_split(
    const float* __restrict__ S,
    __nv_bfloat16* __restrict__ Dh, __nv_bfloat16* __restrict__ Dl)
{
    __shared__ float tile[32][33];
    int x = blockIdx.x * 32 + threadIdx.x;
    int y = blockIdx.y * 32 + threadIdx.y;
#pragma unroll
    for (int j = 0; j < 32; j += 8)
        tile[threadIdx.y + j][threadIdx.x] = S[(size_t)(y + j) * DIM + x];
    __syncthreads();
    x = blockIdx.y * 32 + threadIdx.x;
    y = blockIdx.x * 32 + threadIdx.y;
#pragma unroll
    for (int j = 0; j < 32; j += 8) {
        float v = tile[threadIdx.x][threadIdx.y + j];
        __nv_bfloat16 h, l;
        bsplit(v, h, l);
        Dh[(size_t)(y + j) * DIM + x] = h;
        Dl[(size_t)(y + j) * DIM + x] = l;
    }
}

// ============================================================
// elementwise fp32 -> bf16 hi/lo split
// ============================================================
__global__ __launch_bounds__(256) void split_convert(
    const float* __restrict__ S,
    __nv_bfloat16* __restrict__ Dh, __nv_bfloat16* __restrict__ Dl, int n4)
{
    int i = blockIdx.x * 256 + threadIdx.x;
    if (i >= n4) return;
    float4 v = *(const float4*)&S[i * 4];
    __nv_bfloat16 h0,h1,h2,h3,l0,l1,l2,l3;
    bsplit(v.x, h0, l0); bsplit(v.y, h1, l1);
    bsplit(v.z, h2, l2); bsplit(v.w, h3, l3);
    __nv_bfloat162* ph = (__nv_bfloat162*)&Dh[i * 4];
    __nv_bfloat162* pl = (__nv_bfloat162*)&Dl[i * 4];
    ph[0] = __nv_bfloat162(h0, h1); ph[1] = __nv_bfloat162(h2, h3);
    pl[0] = __nv_bfloat162(l0, l1); pl[1] = __nv_bfloat162(l2, l3);
}

// ============================================================
// bf16x3 GEMM core: C[m][n] = alpha*sum_k A[m][k]B[n][k] (+bias)
// Tile M128 x N64, BK=32, 8 warps of 32x32, ldmatrix fragments,
// cp.async double-buffered, 60KB smem -> 2 CTAs/SM.
// mode: 0 = fp32 C[row*ldc+col]; 1 = fp32 remap [h][row][t];
//       2 = bf16 split remap to Ch/Cl.
// ============================================================
#define BK        32
#define SWW       20                 // words per smem row (16 data + 4 pad)
#define A_PLANE_B 10240              // 128*20*4
#define B_PLANE_B 5120               // 64*20*4
#define B_SECT    20480              // 2*A_PLANE_B
#define BUF_B     30720              // bytes per buffer
#define GSMEM_BYTES 61440

__device__ __forceinline__ void stage_tile(
    unsigned sbase, int buf, int k0, int tid,
    const __nv_bfloat16* gAh, const __nv_bfloat16* gAl,
    const __nv_bfloat16* gBh, const __nv_bfloat16* gBl,
    int lda, int ldb)
{
    const unsigned base = sbase + buf * BUF_B;
#pragma unroll
    for (int i = 0; i < 6; i++) {
        const int idx = tid + i * 256;
        if (idx < 1024) {            // A planes: 2 x 512 chunks
            const int plane = idx >> 9;
            const int rem = idx & 511;
            const int row = rem >> 2, c4 = rem & 3;
            const __nv_bfloat16* src =
                (plane ? gAl : gAh) + (size_t)row * lda + k0 + c4 * 8;
            const unsigned dst = base + plane * A_PLANE_B + row * 80 + c4 * 16;
            asm volatile("cp.async.cg.shared.global [%0], [%1], 16;"
                         :: "r"(dst), "l"(src));
        } else {                     // B planes: 2 x 256 chunks
            const int idx2 = idx - 1024;
            const int plane = idx2 >> 8;
            const int rem = idx2 & 255;
            const int row = rem >> 2, c4 = rem & 3;
            const __nv_bfloat16* src =
                (plane ? gBl : gBh) + (size_t)row * ldb + k0 + c4 * 8;
            const unsigned dst = base + B_SECT + plane * B_PLANE_B + row * 80 + c4 * 16;
            asm volatile("cp.async.cg.shared.global [%0], [%1], 16;"
                         :: "r"(dst), "l"(src));
        }
    }
    asm volatile("cp.async.commit_group;");
}

__device__ __forceinline__ void gemm_core(
    unsigned sbase,
    const __nv_bfloat16* __restrict__ Ah, const __nv_bfloat16* __restrict__ Al,
    const __nv_bfloat16* __restrict__ Bh, const __nv_bfloat16* __restrict__ Bl,
    const float* __restrict__ bias, float* __restrict__ C,
    __nv_bfloat16* __restrict__ Ch, __nv_bfloat16* __restrict__ Cl,
    int K, int lda, int ldb, int ldc, float alpha, int mode,
    int m0, int n0)
{
    const int tid  = threadIdx.x;
    const int lane = tid & 31;
    const int wid  = tid >> 5;
    const int wm   = (wid >> 1) * 32;     // 0,32,64,96
    const int wn   = (wid & 1) * 32;      // 0,32
    const int g    = lane >> 2;
    const int t    = lane & 3;
    const int sub    = lane >> 3;
    const int subrow = lane & 7;
    // ldmatrix per-lane offsets (words), relative to tile-base row
    const int a_off = ((sub & 1) * 8 + subrow) * SWW + (sub >> 1) * 4;
    const int b_off = ((sub >> 1) * 8 + subrow) * SWW + (sub & 1) * 4;

    const __nv_bfloat16* gAh = Ah + (size_t)m0 * lda;
    const __nv_bfloat16* gAl = Al + (size_t)m0 * lda;
    const __nv_bfloat16* gBh = Bh + (size_t)n0 * ldb;
    const __nv_bfloat16* gBl = Bl + (size_t)n0 * ldb;

    float acc[2][4][4];
#pragma unroll
    for (int mt = 0; mt < 2; mt++)
#pragma unroll
        for (int nt = 0; nt < 4; nt++)
#pragma unroll
            for (int e = 0; e < 4; e++) acc[mt][nt][e] = 0.0f;

    const int T = K / BK;
    stage_tile(sbase, 0, 0, tid, gAh, gAl, gBh, gBl, lda, ldb);

    for (int tt = 0; tt < T; tt++) {
        if (tt + 1 < T) {
            stage_tile(sbase, (tt + 1) & 1, (tt + 1) * BK, tid,
                       gAh, gAl, gBh, gBl, lda, ldb);
            asm volatile("cp.async.wait_group 1;");
        } else {
            asm volatile("cp.async.wait_group 0;");
        }
        __syncthreads();

        const unsigned base = sbase + (tt & 1) * BUF_B;
#pragma unroll
        for (int ks = 0; ks < 2; ks++) {
            unsigned ah[2][4], al[2][4], bh[4][2], bl[4][2];
#pragma unroll
            for (int mt = 0; mt < 2; mt++) {
                const unsigned ad = base + ((wm + mt * 16) * SWW + ks * 8 + a_off) * 4;
                LDSM4(ah[mt][0], ah[mt][1], ah[mt][2], ah[mt][3], ad);
                LDSM4(al[mt][0], al[mt][1], al[mt][2], al[mt][3], ad + A_PLANE_B);
            }
#pragma unroll
            for (int np = 0; np < 2; np++) {
                const unsigned bd = base + B_SECT +
                                    ((wn + np * 16) * SWW + ks * 8 + b_off) * 4;
                unsigned r0, r1, r2, r3;
                LDSM4(r0, r1, r2, r3, bd);
                bh[2*np][0] = r0; bh[2*np][1] = r1;
                bh[2*np+1][0] = r2; bh[2*np+1][1] = r3;
                LDSM4(r0, r1, r2, r3, bd + B_PLANE_B);
                bl[2*np][0] = r0; bl[2*np][1] = r1;
                bl[2*np+1][0] = r2; bl[2*np+1][1] = r3;
            }
#pragma unroll
            for (int mt = 0; mt < 2; mt++)
#pragma unroll
                for (int nt = 0; nt < 4; nt++) {
                    mma_bf16(acc[mt][nt], al[mt], bh[nt]);
                    mma_bf16(acc[mt][nt], ah[mt], bl[nt]);
                    mma_bf16(acc[mt][nt], ah[mt], bh[nt]);
                }
        }
        __syncthreads();
    }

    // ---- epilogue ----
#pragma unroll
    for (int mt = 0; mt < 2; mt++) {
        const int rowA = m0 + wm + mt * 16 + g;
        const int rowB = rowA + 8;
#pragma unroll
        for (int nt = 0; nt < 4; nt++) {
            const int col = n0 + wn + nt * 8 + 2 * t;
            float bx = 0.0f, by = 0.0f;
            if (bias) { bx = bias[col]; by = bias[col + 1]; }
            float lox = acc[mt][nt][0] * alpha + bx;
            float loy = acc[mt][nt][1] * alpha + by;
            float hix = acc[mt][nt][2] * alpha + bx;
            float hiy = acc[mt][nt][3] * alpha + by;
            if (mode == 0) {
                *(float2*)&C[(size_t)rowA * ldc + col] = make_float2(lox, loy);
                *(float2*)&C[(size_t)rowB * ldc + col] = make_float2(hix, hiy);
            } else if (mode == 1) {
                const int h = col >> 6, tc = col & 63;
                *(float2*)&C[((size_t)h * SQ + rowA) * HD + tc] = make_float2(lox, loy);
                *(float2*)&C[((size_t)h * SQ + rowB) * HD + tc] = make_float2(hix, hiy);
            } else {
                const int h = col >> 6, tc = col & 63;
                __nv_bfloat16 h0,h1,h2,h3,l0,l1,l2,l3;
                bsplit(lox, h0, l0); bsplit(loy, h1, l1);
                bsplit(hix, h2, l2); bsplit(hiy, h3, l3);
                *(__nv_bfloat162*)&Ch[((size_t)h * SQ + rowA) * HD + tc] = __nv_bfloat162(h0, h1);
                *(__nv_bfloat162*)&Cl[((size_t)h * SQ + rowA) * HD + tc] = __nv_bfloat162(l0, l1);
                *(__nv_bfloat162*)&Ch[((size_t)h * SQ + rowB) * HD + tc] = __nv_bfloat162(h2, h3);
                *(__nv_bfloat162*)&Cl[((size_t)h * SQ + rowB) * HD + tc] = __nv_bfloat162(l2, l3);
            }
        }
    }
}

// ---- generic z-batched wrapper (scores, out-proj) ----
__global__ __launch_bounds__(256, 2) void nt_bf16x3_gemm(
    const __nv_bfloat16* __restrict__ Ah, const __nv_bfloat16* __restrict__ Al,
    const __nv_bfloat16* __restrict__ Bh, const __nv_bfloat16* __restrict__ Bl,
    const float* __restrict__ bias, float* __restrict__ C,
    int K, int lda, int ldb, int ldc, float alpha,
    long strA, long strB, long strC)
{
    extern __shared__ unsigned sm[];
    unsigned sbase = (unsigned)__cvta_generic_to_shared(sm);
    gemm_core(sbase,
              Ah + (size_t)blockIdx.z * strA, Al + (size_t)blockIdx.z * strA,
              Bh + (size_t)blockIdx.z * strB, Bl + (size_t)blockIdx.z * strB,
              bias, C + (size_t)blockIdx.z * strC, nullptr, nullptr,
              K, lda, ldb, ldc, alpha, 0,
              blockIdx.y * 128, blockIdx.x * 64);
}

// ---- fused QKV projection: blockIdx.z selects Q/K/V ----
__global__ __launch_bounds__(256, 2) void qkv_gemm(
    const float* __restrict__ bq, const float* __restrict__ bk,
    const float* __restrict__ bv)
{
    extern __shared__ unsigned sm[];
    unsigned sbase = (unsigned)__cvta_generic_to_shared(sm);
    const int z = blockIdx.z;
    const size_t DD = (size_t)DIM * DIM;
    const float* bias = (z == 0) ? bq : (z == 1) ? bk : bv;
    float* C = (z == 2) ? g_V : nullptr;
    __nv_bfloat16* Ch = (z == 0) ? g_Qh : (z == 1) ? g_Kh : nullptr;
    __nv_bfloat16* Cl = (z == 0) ? g_Ql : (z == 1) ? g_Kl : nullptr;
    gemm_core(sbase, g_xh, g_xl, g_WTh + z * DD, g_WTl + z * DD,
              bias, C, Ch, Cl,
              DIM, DIM, DIM, DIM, 1.0f, (z == 2) ? 1 : 2,
              blockIdx.y * 128, blockIdx.x * 64);
}

// ============================================================
// Per-head V column sums
// ============================================================
__global__ __launch_bounds__(256) void vsum_kernel()
{
    const int h = blockIdx.x;
    const int t = threadIdx.x & 63;
    const int g = threadIdx.x >> 6;
    const float* Vh = g_V + (size_t)h * SQ * HD;
    float s = 0.0f;
    for (int r = g * 512; r < (g + 1) * 512; ++r)
        s += Vh[(size_t)r * HD + t];
    __shared__ float red[4][64];
    red[g][t] = s;
    __syncthreads();
    if (g == 0)
        g_vsum[h * HD + t] = red[0][t] + red[1][t] + red[2][t] + red[3][t];
}

// ============================================================
// Top-16 + sparse softmax + PV gather. One warp per (h, q).
// ============================================================
__global__ __launch_bounds__(128) void topk_attend()
{
    const unsigned FULL = 0xffffffffu;
    const int gwarp = (blockIdx.x * 128 + threadIdx.x) >> 5;
    const int lane  = threadIdx.x & 31;
    const int h = gwarp >> 11;
    const int q = gwarp & 2047;

    const float* row = g_scores + ((size_t)h * SQ + q) * SQ;

    float lv[16];
    int   li[16];
#pragma unroll
    for (int i = 0; i < 16; i++) { lv[i] = -1e30f; li[i] = 0; }

#pragma unroll 4
    for (int c = 0; c < 16; c++) {
        const int base = c * 128 + lane * 4;
        float4 v4 = *(const float4*)&row[base];
        float vals[4] = {v4.x, v4.y, v4.z, v4.w};
#pragma unroll
        for (int j = 0; j < 4; j++) {
            const float val = vals[j];
            if (val > lv[15]) {
                lv[15] = val; li[15] = base + j;
#pragma unroll
                for (int p = 15; p >= 1; --p) {
                    if (lv[p] > lv[p - 1]) {
                        float tv = lv[p]; lv[p] = lv[p - 1]; lv[p - 1] = tv;
                        int   ti = li[p]; li[p] = li[p - 1]; li[p - 1] = ti;
                    }
                }
            }
        }
    }

    float fv = -1e30f;
    int   fi = 0;
    for (int r = 0; r < 16; r++) {
        float bv = lv[0]; int bi = li[0]; int bl = lane;
#pragma unroll
        for (int off = 16; off > 0; off >>= 1) {
            float ov = __shfl_down_sync(FULL, bv, off);
            int   oi = __shfl_down_sync(FULL, bi, off);
            int   ol = __shfl_down_sync(FULL, bl, off);
            if (ov > bv) { bv = ov; bi = oi; bl = ol; }
        }
        bv = __shfl_sync(FULL, bv, 0);
        bi = __shfl_sync(FULL, bi, 0);
        bl = __shfl_sync(FULL, bl, 0);
        if (lane == bl) {
#pragma unroll
            for (int p = 0; p < 15; p++) { lv[p] = lv[p + 1]; li[p] = li[p + 1]; }
            lv[15] = -1e30f;
        }
        if (lane == r) { fv = bv; fi = bi; }
    }

    float m = __shfl_sync(FULL, fv, 0);
    m = fmaxf(m, 0.0f);
    float e = (lane < 16) ? expf(fv - m) : 0.0f;
    float z = e;
#pragma unroll
    for (int off = 16; off > 0; off >>= 1)
        z += __shfl_xor_sync(FULL, z, off);
    const float e0 = expf(-m);
    const float Z  = z + (float)(SQ - FACT) * e0;
    const float p0 = e0 / Z;
    const float w  = e / Z - p0;

    const float* Vh = g_V + (size_t)h * SQ * HD;
    float acc0 = p0 * g_vsum[h * HD + lane];
    float acc1 = p0 * g_vsum[h * HD + lane + 32];
#pragma unroll
    for (int i = 0; i < 16; i++) {
        const float wi  = __shfl_sync(FULL, w,  i);
        const int   idx = __shfl_sync(FULL, fi, i);
        const float* vr = Vh + (size_t)idx * HD;
        acc0 = fmaf(wi, vr[lane],      acc0);
        acc1 = fmaf(wi, vr[lane + 32], acc1);
    }
    float* o = g_attn + (size_t)q * DIM + h * HD;
    o[lane]      = acc0;
    o[lane + 32] = acc1;
}

// ============================================================
extern "C" void kernel_launch(void* const* d_in, const int* in_sizes, int n_in,
                              void* d_out, int out_size)
{
    const float* x  = (const float*)d_in[0];
    const float* Wq = (const float*)d_in[1];
    const float* bq = (const float*)d_in[2];
    const float* Wk = (const float*)d_in[3];
    const float* bk = (const float*)d_in[4];
    const float* Wv = (const float*)d_in[5];
    const float* bv = (const float*)d_in[6];
    const float* Wo = (const float*)d_in[7];
    const float* bo = (const float*)d_in[8];
    float* out = (float*)d_out;

    float *attnp, *scoresp;
    __nv_bfloat16 *xh, *xl, *ath, *atl, *WTh, *WTl, *Qh, *Ql, *Kh, *Kl;
    cudaGetSymbolAddress((void**)&attnp,   g_attn);
    cudaGetSymbolAddress((void**)&scoresp, g_scores);
    cudaGetSymbolAddress((void**)&xh,  g_xh);  cudaGetSymbolAddress((void**)&xl,  g_xl);
    cudaGetSymbolAddress((void**)&ath, g_ath); cudaGetSymbolAddress((void**)&atl, g_atl);
    cudaGetSymbolAddress((void**)&WTh, g_WTh); cudaGetSymbolAddress((void**)&WTl, g_WTl);
    cudaGetSymbolAddress((void**)&Qh,  g_Qh);  cudaGetSymbolAddress((void**)&Ql,  g_Ql);
    cudaGetSymbolAddress((void**)&Kh,  g_Kh);  cudaGetSymbolAddress((void**)&Kl,  g_Kl);

    static int smem_set = 0;
    if (!smem_set) {
        cudaFuncSetAttribute(nt_bf16x3_gemm,
                             cudaFuncAttributeMaxDynamicSharedMemorySize, GSMEM_BYTES);
        cudaFuncSetAttribute(qkv_gemm,
                             cudaFuncAttributeMaxDynamicSharedMemorySize, GSMEM_BYTES);
        smem_set = 1;
    }

    const size_t DD = (size_t)DIM * DIM;

    dim3 gT(DIM / 32, DIM / 32);
    dim3 bT(32, 8);
    transpose_split<<<gT, bT>>>(Wq, WTh,          WTl);
    transpose_split<<<gT, bT>>>(Wk, WTh + DD,     WTl + DD);
    transpose_split<<<gT, bT>>>(Wv, WTh + 2 * DD, WTl + 2 * DD);
    transpose_split<<<gT, bT>>>(Wo, WTh + 3 * DD, WTl + 3 * DD);

    split_convert<<<(SQ * DIM / 4 + 255) / 256, 256>>>(x, xh, xl, SQ * DIM / 4);

    // fused Q/K/V projections (z = 0,1,2)
    dim3 gQKV(DIM / 64, SQ / 128, 3);   // (16, 16, 3)
    qkv_gemm<<<gQKV, 256, GSMEM_BYTES>>>(bq, bk, bv);

    vsum_kernel<<<NH, 256>>>();

    // scores: per-head NT GEMM over bf16 planes
    dim3 gSc(SQ / 64, SQ / 128, NH);    // (32, 16, 16)
    nt_bf16x3_gemm<<<gSc, 256, GSMEM_BYTES>>>(
        Qh, Ql, Kh, Kl, nullptr, scoresp,
        HD, HD, HD, SQ, 0.125f,
        (long)SQ * HD, (long)SQ * HD, (long)SQ * SQ);

    topk_attend<<<(NH * SQ) / 4, 128>>>();

    split_convert<<<(SQ * DIM / 4 + 255) / 256, 256>>>(attnp, ath, atl, SQ * DIM / 4);

    // output projection
    dim3 gO(DIM / 64, SQ / 128, 1);     // (16, 16, 1)
    nt_bf16x3_gemm<<<gO, 256, GSMEM_BYTES>>>(
        ath, atl, WTh + 3 * DD, WTl + 3 * DD, bo, out,
        DIM, DIM, DIM, DIM, 1.0f, 0, 0, 0);
}

// round 12
// speedup vs baseline: 1.0594x; 1.0163x over previous
#include <cuda_runtime.h>
#include <cuda_bf16.h>
#include <math.h>

#define SQ   2048
#define DIM  1024
#define NH   16
#define HD   64
#define FACT 16

// ---- scratch (device globals: the sanctioned no-alloc scratch path) ----
__device__ float g_V[NH * SQ * HD];              // 8 MB fp32 [h][s][hd]
__device__ float g_scores[(size_t)NH * SQ * SQ]; // 256 MB fp32 [h][q][k]
__device__ float g_vsum[NH * HD];
__device__ float g_vsum_part[64][HD];

// bf16 split planes
__device__ __nv_bfloat16 g_xh[SQ * DIM],  g_xl[SQ * DIM];
__device__ __nv_bfloat16 g_ath[SQ * DIM], g_atl[SQ * DIM];   // attn out planes
__device__ __nv_bfloat16 g_WTh[4 * DIM * DIM], g_WTl[4 * DIM * DIM];
__device__ __nv_bfloat16 g_Qh[NH * SQ * HD], g_Ql[NH * SQ * HD];
__device__ __nv_bfloat16 g_Kh[NH * SQ * HD], g_Kl[NH * SQ * HD];

// ============================================================
// helpers
// ============================================================
__device__ __forceinline__ void bsplit(float v, __nv_bfloat16& h, __nv_bfloat16& l) {
    h = __float2bfloat16(v);
    l = __float2bfloat16(v - __bfloat162float(h));
}

__device__ __forceinline__ void mma_bf16(float* c, const unsigned* a, const unsigned* b) {
    asm volatile(
        "mma.sync.aligned.m16n8k16.row.col.f32.bf16.bf16.f32 "
        "{%0,%1,%2,%3}, {%4,%5,%6,%7}, {%8,%9}, {%0,%1,%2,%3};"
        : "+f"(c[0]), "+f"(c[1]), "+f"(c[2]), "+f"(c[3])
        : "r"(a[0]), "r"(a[1]), "r"(a[2]), "r"(a[3]),
          "r"(b[0]), "r"(b[1]));
}

#define LDSM4(R0, R1, R2, R3, A)                                          \
    asm volatile("ldmatrix.sync.aligned.m8n8.x4.shared.b16 "              \
                 "{%0,%1,%2,%3}, [%4];"                                   \
                 : "=r"(R0), "=r"(R1), "=r"(R2), "=r"(R3) : "r"(A))

// ============================================================
// fused 4x 1024x1024 transpose + bf16 hi/lo split (z = which W)
// ============================================================
__global__ __launch_bounds__(256) void transpose_split4(
    const float* __restrict__ W0, const float* __restrict__ W1,
    const float* __restrict__ W2, const float* __restrict__ W3,
    __nv_bfloat16* __restrict__ Dh, __nv_bfloat16* __restrict__ Dl)
{
    __shared__ float tile[32][33];
    const int z = blockIdx.z;
    const float* S = (z == 0) ? W0 : (z == 1) ? W1 : (z == 2) ? W2 : W3;
    const size_t off = (size_t)z * DIM * DIM;
    int x = blockIdx.x * 32 + threadIdx.x;
    int y = blockIdx.y * 32 + threadIdx.y;
#pragma unroll
    for (int j = 0; j < 32; j += 8)
        tile[threadIdx.y + j][threadIdx.x] = S[(size_t)(y + j) * DIM + x];
    __syncthreads();
    x = blockIdx.y * 32 + threadIdx.x;
    y = blockIdx.x * 32 + threadIdx.y;
#pragma unroll
    for (int j = 0; j < 32; j += 8) {
        float v = tile[threadIdx.x][threadIdx.y + j];
        __nv_bfloat16 h, l;
        bsplit(v, h, l);
        Dh[off + (size_t)(y + j) * DIM + x] = h;
        Dl[off + (size_t)(y + j) * DIM + x] = l;
    }
}

// ============================================================
// elementwise fp32 -> bf16 hi/lo split (x only)
// ============================================================
__global__ __launch_bounds__(256) void split_convert(
    const float* __restrict__ S,
    __nv_bfloat16* __restrict__ Dh, __nv_bfloat16* __restrict__ Dl, int n4)
{
    int i = blockIdx.x * 256 + threadIdx.x;
    if (i >= n4) return;
    float4 v = *(const float4*)&S[i * 4];
    __nv_bfloat16 h0,h1,h2,h3,l0,l1,l2,l3;
    bsplit(v.x, h0, l0); bsplit(v.y, h1, l1);
    bsplit(v.z, h2, l2); bsplit(v.w, h3, l3);
    __nv_bfloat162* ph = (__nv_bfloat162*)&Dh[i * 4];
    __nv_bfloat162* pl = (__nv_bfloat162*)&Dl[i * 4];
    ph[0] = __nv_bfloat162(h0, h1); ph[1] = __nv_bfloat162(h2, h3);
    pl[0] = __nv_bfloat162(l0, l1); pl[1] = __nv_bfloat162(l2, l3);
}

// ============================================================
// bf16x3 GEMM core. Tile M128 x N64, BK=32, 8 warps, ldmatrix,
// cp.async double-buffered, 60KB smem -> 2 CTAs/SM.
// mode: 0 = fp32 C[row*ldc+col]; 1 = fp32 remap [h][row][t];
//       2 = bf16 split remap to Ch/Cl.
// ============================================================
#define BK        32
#define SWW       20
#define A_PLANE_B 10240
#define B_PLANE_B 5120
#define B_SECT    20480
#define BUF_B     30720
#define GSMEM_BYTES 61440

__device__ __forceinline__ void stage_tile(
    unsigned sbase, int buf, int k0, int tid,
    const __nv_bfloat16* gAh, const __nv_bfloat16* gAl,
    const __nv_bfloat16* gBh, const __nv_bfloat16* gBl,
    int lda, int ldb)
{
    const unsigned base = sbase + buf * BUF_B;
#pragma unroll
    for (int i = 0; i < 6; i++) {
        const int idx = tid + i * 256;
        if (idx < 1024) {
            const int plane = idx >> 9;
            const int rem = idx & 511;
            const int row = rem >> 2, c4 = rem & 3;
            const __nv_bfloat16* src =
                (plane ? gAl : gAh) + (size_t)row * lda + k0 + c4 * 8;
            const unsigned dst = base + plane * A_PLANE_B + row * 80 + c4 * 16;
            asm volatile("cp.async.cg.shared.global [%0], [%1], 16;"
                         :: "r"(dst), "l"(src));
        } else {
            const int idx2 = idx - 1024;
            const int plane = idx2 >> 8;
            const int rem = idx2 & 255;
            const int row = rem >> 2, c4 = rem & 3;
            const __nv_bfloat16* src =
                (plane ? gBl : gBh) + (size_t)row * ldb + k0 + c4 * 8;
            const unsigned dst = base + B_SECT + plane * B_PLANE_B + row * 80 + c4 * 16;
            asm volatile("cp.async.cg.shared.global [%0], [%1], 16;"
                         :: "r"(dst), "l"(src));
        }
    }
    asm volatile("cp.async.commit_group;");
}

__device__ __forceinline__ void gemm_core(
    unsigned sbase,
    const __nv_bfloat16* __restrict__ Ah, const __nv_bfloat16* __restrict__ Al,
    const __nv_bfloat16* __restrict__ Bh, const __nv_bfloat16* __restrict__ Bl,
    const float* __restrict__ bias, float* __restrict__ C,
    __nv_bfloat16* __restrict__ Ch, __nv_bfloat16* __restrict__ Cl,
    int K, int lda, int ldb, int ldc, float alpha, int mode,
    int m0, int n0)
{
    const int tid  = threadIdx.x;
    const int lane = tid & 31;
    const int wid  = tid >> 5;
    const int wm   = (wid >> 1) * 32;
    const int wn   = (wid & 1) * 32;
    const int g    = lane >> 2;
    const int t    = lane & 3;
    const int sub    = lane >> 3;
    const int subrow = lane & 7;
    const int a_off = ((sub & 1) * 8 + subrow) * SWW + (sub >> 1) * 4;
    const int b_off = ((sub >> 1) * 8 + subrow) * SWW + (sub & 1) * 4;

    const __nv_bfloat16* gAh = Ah + (size_t)m0 * lda;
    const __nv_bfloat16* gAl = Al + (size_t)m0 * lda;
    const __nv_bfloat16* gBh = Bh + (size_t)n0 * ldb;
    const __nv_bfloat16* gBl = Bl + (size_t)n0 * ldb;

    float acc[2][4][4];
#pragma unroll
    for (int mt = 0; mt < 2; mt++)
#pragma unroll
        for (int nt = 0; nt < 4; nt++)
#pragma unroll
            for (int e = 0; e < 4; e++) acc[mt][nt][e] = 0.0f;

    const int T = K / BK;
    stage_tile(sbase, 0, 0, tid, gAh, gAl, gBh, gBl, lda, ldb);

    for (int tt = 0; tt < T; tt++) {
        if (tt + 1 < T) {
            stage_tile(sbase, (tt + 1) & 1, (tt + 1) * BK, tid,
                       gAh, gAl, gBh, gBl, lda, ldb);
            asm volatile("cp.async.wait_group 1;");
        } else {
            asm volatile("cp.async.wait_group 0;");
        }
        __syncthreads();

        const unsigned base = sbase + (tt & 1) * BUF_B;
#pragma unroll
        for (int ks = 0; ks < 2; ks++) {
            unsigned ah[2][4], al[2][4], bh[4][2], bl[4][2];
#pragma unroll
            for (int mt = 0; mt < 2; mt++) {
                const unsigned ad = base + ((wm + mt * 16) * SWW + ks * 8 + a_off) * 4;
                LDSM4(ah[mt][0], ah[mt][1], ah[mt][2], ah[mt][3], ad);
                LDSM4(al[mt][0], al[mt][1], al[mt][2], al[mt][3], ad + A_PLANE_B);
            }
#pragma unroll
            for (int np = 0; np < 2; np++) {
                const unsigned bd = base + B_SECT +
                                    ((wn + np * 16) * SWW + ks * 8 + b_off) * 4;
                unsigned r0, r1, r2, r3;
                LDSM4(r0, r1, r2, r3, bd);
                bh[2*np][0] = r0; bh[2*np][1] = r1;
                bh[2*np+1][0] = r2; bh[2*np+1][1] = r3;
                LDSM4(r0, r1, r2, r3, bd + B_PLANE_B);
                bl[2*np][0] = r0; bl[2*np][1] = r1;
                bl[2*np+1][0] = r2; bl[2*np+1][1] = r3;
            }
#pragma unroll
            for (int mt = 0; mt < 2; mt++)
#pragma unroll
                for (int nt = 0; nt < 4; nt++) {
                    mma_bf16(acc[mt][nt], al[mt], bh[nt]);
                    mma_bf16(acc[mt][nt], ah[mt], bl[nt]);
                    mma_bf16(acc[mt][nt], ah[mt], bh[nt]);
                }
        }
        __syncthreads();
    }

    // ---- epilogue ----
#pragma unroll
    for (int mt = 0; mt < 2; mt++) {
        const int rowA = m0 + wm + mt * 16 + g;
        const int rowB = rowA + 8;
#pragma unroll
        for (int nt = 0; nt < 4; nt++) {
            const int col = n0 + wn + nt * 8 + 2 * t;
            float bx = 0.0f, by = 0.0f;
            if (bias) { bx = bias[col]; by = bias[col + 1]; }
            float lox = acc[mt][nt][0] * alpha + bx;
            float loy = acc[mt][nt][1] * alpha + by;
            float hix = acc[mt][nt][2] * alpha + bx;
            float hiy = acc[mt][nt][3] * alpha + by;
            if (mode == 0) {
                *(float2*)&C[(size_t)rowA * ldc + col] = make_float2(lox, loy);
                *(float2*)&C[(size_t)rowB * ldc + col] = make_float2(hix, hiy);
            } else if (mode == 1) {
                const int h = col >> 6, tc = col & 63;
                *(float2*)&C[((size_t)h * SQ + rowA) * HD + tc] = make_float2(lox, loy);
                *(float2*)&C[((size_t)h * SQ + rowB) * HD + tc] = make_float2(hix, hiy);
            } else {
                const int h = col >> 6, tc = col & 63;
                __nv_bfloat16 h0,h1,h2,h3,l0,l1,l2,l3;
                bsplit(lox, h0, l0); bsplit(loy, h1, l1);
                bsplit(hix, h2, l2); bsplit(hiy, h3, l3);
                *(__nv_bfloat162*)&Ch[((size_t)h * SQ + rowA) * HD + tc] = __nv_bfloat162(h0, h1);
                *(__nv_bfloat162*)&Cl[((size_t)h * SQ + rowA) * HD + tc] = __nv_bfloat162(l0, l1);
                *(__nv_bfloat162*)&Ch[((size_t)h * SQ + rowB) * HD + tc] = __nv_bfloat162(h2, h3);
                *(__nv_bfloat162*)&Cl[((size_t)h * SQ + rowB) * HD + tc] = __nv_bfloat162(l2, l3);
            }
        }
    }
}

// ---- generic z-batched wrapper (scores, out-proj) ----
__global__ __launch_bounds__(256, 2) void nt_bf16x3_gemm(
    const __nv_bfloat16* __restrict__ Ah, const __nv_bfloat16* __restrict__ Al,
    const __nv_bfloat16* __restrict__ Bh, const __nv_bfloat16* __restrict__ Bl,
    const float* __restrict__ bias, float* __restrict__ C,
    int K, int lda, int ldb, int ldc, float alpha,
    long strA, long strB, long strC)
{
    extern __shared__ unsigned sm[];
    unsigned sbase = (unsigned)__cvta_generic_to_shared(sm);
    gemm_core(sbase,
              Ah + (size_t)blockIdx.z * strA, Al + (size_t)blockIdx.z * strA,
              Bh + (size_t)blockIdx.z * strB, Bl + (size_t)blockIdx.z * strB,
              bias, C + (size_t)blockIdx.z * strC, nullptr, nullptr,
              K, lda, ldb, ldc, alpha, 0,
              blockIdx.y * 128, blockIdx.x * 64);
}

// ---- fused QKV projection: blockIdx.z selects Q/K/V ----
__global__ __launch_bounds__(256, 2) void qkv_gemm(
    const float* __restrict__ bq, const float* __restrict__ bk,
    const float* __restrict__ bv)
{
    extern __shared__ unsigned sm[];
    unsigned sbase = (unsigned)__cvta_generic_to_shared(sm);
    const int z = blockIdx.z;
    const size_t DD = (size_t)DIM * DIM;
    const float* bias = (z == 0) ? bq : (z == 1) ? bk : bv;
    float* C = (z == 2) ? g_V : nullptr;
    __nv_bfloat16* Ch = (z == 0) ? g_Qh : (z == 1) ? g_Kh : nullptr;
    __nv_bfloat16* Cl = (z == 0) ? g_Ql : (z == 1) ? g_Kl : nullptr;
    gemm_core(sbase, g_xh, g_xl, g_WTh + z * DD, g_WTl + z * DD,
              bias, C, Ch, Cl,
              DIM, DIM, DIM, DIM, 1.0f, (z == 2) ? 1 : 2,
              blockIdx.y * 128, blockIdx.x * 64);
}

// ============================================================
// V column sums: stage A (64 partial blocks) + stage B (reduce)
// ============================================================
__global__ __launch_bounds__(256) void vsum_part()
{
    const int h  = blockIdx.x >> 2;
    const int qd = blockIdx.x & 3;
    const int t = threadIdx.x & 63;
    const int g = threadIdx.x >> 6;
    const float* Vh = g_V + (size_t)h * SQ * HD + (size_t)(qd * 512 + g * 128) * HD;
    float s = 0.0f;
    for (int r = 0; r < 128; ++r)
        s += Vh[(size_t)r * HD + t];
    __shared__ float red[4][64];
    red[g][t] = s;
    __syncthreads();
    if (g == 0)
        g_vsum_part[blockIdx.x][t] = red[0][t] + red[1][t] + red[2][t] + red[3][t];
}

__global__ __launch_bounds__(256) void vsum_reduce()
{
    const int i = blockIdx.x * 256 + threadIdx.x;   // 0..1023
    const int h = i >> 6, t = i & 63;
    g_vsum[i] = g_vsum_part[h * 4 + 0][t] + g_vsum_part[h * 4 + 1][t]
              + g_vsum_part[h * 4 + 2][t] + g_vsum_part[h * 4 + 3][t];
}

// ============================================================
// Top-16 (exact fp32) + sparse softmax + V gather. One warp per
// (h, q). Writes output directly as bf16 hi/lo planes [s][d].
// ============================================================
__global__ __launch_bounds__(128) void topk_attend()
{
    const unsigned FULL = 0xffffffffu;
    const int gwarp = (blockIdx.x * 128 + threadIdx.x) >> 5;
    const int lane  = threadIdx.x & 31;
    const int h = gwarp >> 11;
    const int q = gwarp & 2047;

    const float* row = g_scores + ((size_t)h * SQ + q) * SQ;

    // ---- per-lane sorted (desc) top-16 over 64 strided fp32 ----
    float lv[16];
    int   li[16];
#pragma unroll
    for (int i = 0; i < 16; i++) { lv[i] = -1e30f; li[i] = 0; }

#pragma unroll 4
    for (int c = 0; c < 16; c++) {
        const int base = c * 128 + lane * 4;
        float4 v4 = *(const float4*)&row[base];
        float vals[4] = {v4.x, v4.y, v4.z, v4.w};
#pragma unroll
        for (int j = 0; j < 4; j++) {
            const float val = vals[j];
            if (val > lv[15]) {
                lv[15] = val; li[15] = base + j;
#pragma unroll
                for (int p = 15; p >= 1; --p) {
                    if (lv[p] > lv[p - 1]) {
                        float tv = lv[p]; lv[p] = lv[p - 1]; lv[p - 1] = tv;
                        int   ti = li[p]; li[p] = li[p - 1]; li[p - 1] = ti;
                    }
                }
            }
        }
    }

    // ---- 16-round warp argmax merge; lane r keeps the r-th ----
    float fv = -1e30f;
    int   fi = 0;
    for (int r = 0; r < 16; r++) {
        float bv = lv[0]; int bi = li[0]; int bl = lane;
#pragma unroll
        for (int off = 16; off > 0; off >>= 1) {
            float ov = __shfl_down_sync(FULL, bv, off);
            int   oi = __shfl_down_sync(FULL, bi, off);
            int   ol = __shfl_down_sync(FULL, bl, off);
            if (ov > bv) { bv = ov; bi = oi; bl = ol; }
        }
        bv = __shfl_sync(FULL, bv, 0);
        bi = __shfl_sync(FULL, bi, 0);
        bl = __shfl_sync(FULL, bl, 0);
        if (lane == bl) {
#pragma unroll
            for (int p = 0; p < 15; p++) { lv[p] = lv[p + 1]; li[p] = li[p + 1]; }
            lv[15] = -1e30f;
        }
        if (lane == r) { fv = bv; fi = bi; }
    }

    // ---- sparse softmax (zeros participate) ----
    float m = __shfl_sync(FULL, fv, 0);
    m = fmaxf(m, 0.0f);
    float e = (lane < 16) ? expf(fv - m) : 0.0f;
    float z = e;
#pragma unroll
    for (int off = 16; off > 0; off >>= 1)
        z += __shfl_xor_sync(FULL, z, off);
    const float e0 = expf(-m);
    const float Z  = z + (float)(SQ - FACT) * e0;
    const float p0 = e0 / Z;
    const float w  = e / Z - p0;

    // ---- gather 16 V rows + p0 * vsum ----
    const float* Vh = g_V + (size_t)h * SQ * HD;
    float acc0 = p0 * g_vsum[h * HD + lane];
    float acc1 = p0 * g_vsum[h * HD + lane + 32];
#pragma unroll
    for (int i = 0; i < 16; i++) {
        const float wi  = __shfl_sync(FULL, w,  i);
        const int   idx = __shfl_sync(FULL, fi, i);
        const float* vr = Vh + (size_t)idx * HD;
        acc0 = fmaf(wi, vr[lane],      acc0);
        acc1 = fmaf(wi, vr[lane + 32], acc1);
    }
    // write output directly as bf16 hi/lo planes (layout [s][d])
    const size_t o = (size_t)q * DIM + h * HD;
    __nv_bfloat16 h0, l0, h1, l1;
    bsplit(acc0, h0, l0);
    bsplit(acc1, h1, l1);
    g_ath[o + lane]      = h0;
    g_atl[o + lane]      = l0;
    g_ath[o + lane + 32] = h1;
    g_atl[o + lane + 32] = l1;
}

// ============================================================
extern "C" void kernel_launch(void* const* d_in, const int* in_sizes, int n_in,
                              void* d_out, int out_size)
{
    const float* x  = (const float*)d_in[0];
    const float* Wq = (const float*)d_in[1];
    const float* bq = (const float*)d_in[2];
    const float* Wk = (const float*)d_in[3];
    const float* bk = (const float*)d_in[4];
    const float* Wv = (const float*)d_in[5];
    const float* bv = (const float*)d_in[6];
    const float* Wo = (const float*)d_in[7];
    const float* bo = (const float*)d_in[8];
    float* out = (float*)d_out;

    float* scoresp;
    __nv_bfloat16 *xh, *xl, *ath, *atl, *WTh, *WTl, *Qh, *Ql, *Kh, *Kl;
    cudaGetSymbolAddress((void**)&scoresp, g_scores);
    cudaGetSymbolAddress((void**)&xh,  g_xh);  cudaGetSymbolAddress((void**)&xl,  g_xl);
    cudaGetSymbolAddress((void**)&ath, g_ath); cudaGetSymbolAddress((void**)&atl, g_atl);
    cudaGetSymbolAddress((void**)&WTh, g_WTh); cudaGetSymbolAddress((void**)&WTl, g_WTl);
    cudaGetSymbolAddress((void**)&Qh,  g_Qh);  cudaGetSymbolAddress((void**)&Ql,  g_Ql);
    cudaGetSymbolAddress((void**)&Kh,  g_Kh);  cudaGetSymbolAddress((void**)&Kl,  g_Kl);

    static int smem_set = 0;
    if (!smem_set) {
        cudaFuncSetAttribute(nt_bf16x3_gemm,
                             cudaFuncAttributeMaxDynamicSharedMemorySize, GSMEM_BYTES);
        cudaFuncSetAttribute(qkv_gemm,
                             cudaFuncAttributeMaxDynamicSharedMemorySize, GSMEM_BYTES);
        smem_set = 1;
    }

    const size_t DD = (size_t)DIM * DIM;

    // fused weight transposes + splits
    dim3 gT(DIM / 32, DIM / 32, 4);
    dim3 bT(32, 8);
    transpose_split4<<<gT, bT>>>(Wq, Wk, Wv, Wo, WTh, WTl);

    split_convert<<<(SQ * DIM / 4 + 255) / 256, 256>>>(x, xh, xl, SQ * DIM / 4);

    // fused Q/K/V projections
    dim3 gQKV(DIM / 64, SQ / 128, 3);
    qkv_gemm<<<gQKV, 256, GSMEM_BYTES>>>(bq, bk, bv);

    vsum_part<<<64, 256>>>();
    vsum_reduce<<<4, 256>>>();

    // scores: per-head NT GEMM -> fp32 (exact ranking + softmax values)
    dim3 gSc(SQ / 64, SQ / 128, NH);
    nt_bf16x3_gemm<<<gSc, 256, GSMEM_BYTES>>>(
        Qh, Ql, Kh, Kl, nullptr, scoresp,
        HD, HD, HD, SQ, 0.125f,
        (long)SQ * HD, (long)SQ * HD, (long)SQ * SQ);

    topk_attend<<<(NH * SQ) / 4, 128>>>();

    // output projection (reads bf16 planes written by topk)
    dim3 gO(DIM / 64, SQ / 128, 1);
    nt_bf16x3_gemm<<<gO, 256, GSMEM_BYTES>>>(
        ath, atl, WTh + 3 * DD, WTl + 3 * DD, bo, out,
        DIM, DIM, DIM, DIM, 1.0f, 0, 0, 0);
}

// round 13
// speedup vs baseline: 1.7651x; 1.6662x over previous
#include <cuda_runtime.h>
#include <cuda_bf16.h>
#include <math.h>

#define SQ   2048
#define DIM  1024
#define NH   16
#define HD   64
#define FACT 16

// ---- scratch (device globals: the sanctioned no-alloc scratch path) ----
__device__ float g_V[NH * SQ * HD];              // 8 MB fp32 [h][s][hd]
__device__ float g_scores[(size_t)NH * SQ * SQ]; // 256 MB fp32 [h][q][k]
__device__ float g_vsum[NH * HD];
__device__ float g_vsum_part[64][HD];

// bf16 split planes
__device__ __nv_bfloat16 g_xh[SQ * DIM],  g_xl[SQ * DIM];
__device__ __nv_bfloat16 g_ath[SQ * DIM], g_atl[SQ * DIM];   // attn out planes
__device__ __nv_bfloat16 g_WTh[4 * DIM * DIM], g_WTl[4 * DIM * DIM];
__device__ __nv_bfloat16 g_Qh[NH * SQ * HD], g_Ql[NH * SQ * HD];
__device__ __nv_bfloat16 g_Kh[NH * SQ * HD], g_Kl[NH * SQ * HD];

// ============================================================
// helpers
// ============================================================
__device__ __forceinline__ void bsplit(float v, __nv_bfloat16& h, __nv_bfloat16& l) {
    h = __float2bfloat16(v);
    l = __float2bfloat16(v - __bfloat162float(h));
}

__device__ __forceinline__ void mma_bf16(float* c, const unsigned* a, const unsigned* b) {
    asm volatile(
        "mma.sync.aligned.m16n8k16.row.col.f32.bf16.bf16.f32 "
        "{%0,%1,%2,%3}, {%4,%5,%6,%7}, {%8,%9}, {%0,%1,%2,%3};"
        : "+f"(c[0]), "+f"(c[1]), "+f"(c[2]), "+f"(c[3])
        : "r"(a[0]), "r"(a[1]), "r"(a[2]), "r"(a[3]),
          "r"(b[0]), "r"(b[1]));
}

#define LDSM4(R0, R1, R2, R3, A)                                          \
    asm volatile("ldmatrix.sync.aligned.m8n8.x4.shared.b16 "              \
                 "{%0,%1,%2,%3}, [%4];"                                   \
                 : "=r"(R0), "=r"(R1), "=r"(R2), "=r"(R3) : "r"(A))

// ============================================================
// fused 4x 1024x1024 transpose + bf16 hi/lo split (z = which W)
// ============================================================
__global__ __launch_bounds__(256) void transpose_split4(
    const float* __restrict__ W0, const float* __restrict__ W1,
    const float* __restrict__ W2, const float* __restrict__ W3,
    __nv_bfloat16* __restrict__ Dh, __nv_bfloat16* __restrict__ Dl)
{
    __shared__ float tile[32][33];
    const int z = blockIdx.z;
    const float* S = (z == 0) ? W0 : (z == 1) ? W1 : (z == 2) ? W2 : W3;
    const size_t off = (size_t)z * DIM * DIM;
    int x = blockIdx.x * 32 + threadIdx.x;
    int y = blockIdx.y * 32 + threadIdx.y;
#pragma unroll
    for (int j = 0; j < 32; j += 8)
        tile[threadIdx.y + j][threadIdx.x] = S[(size_t)(y + j) * DIM + x];
    __syncthreads();
    x = blockIdx.y * 32 + threadIdx.x;
    y = blockIdx.x * 32 + threadIdx.y;
#pragma unroll
    for (int j = 0; j < 32; j += 8) {
        float v = tile[threadIdx.x][threadIdx.y + j];
        __nv_bfloat16 h, l;
        bsplit(v, h, l);
        Dh[off + (size_t)(y + j) * DIM + x] = h;
        Dl[off + (size_t)(y + j) * DIM + x] = l;
    }
}

// ============================================================
// elementwise fp32 -> bf16 hi/lo split (x only)
// ============================================================
__global__ __launch_bounds__(256) void split_convert(
    const float* __restrict__ S,
    __nv_bfloat16* __restrict__ Dh, __nv_bfloat16* __restrict__ Dl, int n4)
{
    int i = blockIdx.x * 256 + threadIdx.x;
    if (i >= n4) return;
    float4 v = *(const float4*)&S[i * 4];
    __nv_bfloat16 h0,h1,h2,h3,l0,l1,l2,l3;
    bsplit(v.x, h0, l0); bsplit(v.y, h1, l1);
    bsplit(v.z, h2, l2); bsplit(v.w, h3, l3);
    __nv_bfloat162* ph = (__nv_bfloat162*)&Dh[i * 4];
    __nv_bfloat162* pl = (__nv_bfloat162*)&Dl[i * 4];
    ph[0] = __nv_bfloat162(h0, h1); ph[1] = __nv_bfloat162(h2, h3);
    pl[0] = __nv_bfloat162(l0, l1); pl[1] = __nv_bfloat162(l2, l3);
}

// ============================================================
// bf16x3 GEMM core. Tile M128 x N64, BK=32, 8 warps, ldmatrix,
// cp.async double-buffered, 60KB smem -> 2 CTAs/SM.
// mode: 0 = fp32 C[row*ldc+col]; 1 = fp32 remap [h][row][t];
//       2 = bf16 split remap to Ch/Cl.
// ============================================================
#define BK        32
#define SWW       20
#define A_PLANE_B 10240
#define B_PLANE_B 5120
#define B_SECT    20480
#define BUF_B     30720
#define GSMEM_BYTES 61440

__device__ __forceinline__ void stage_tile(
    unsigned sbase, int buf, int k0, int tid,
    const __nv_bfloat16* gAh, const __nv_bfloat16* gAl,
    const __nv_bfloat16* gBh, const __nv_bfloat16* gBl,
    int lda, int ldb)
{
    const unsigned base = sbase + buf * BUF_B;
#pragma unroll
    for (int i = 0; i < 6; i++) {
        const int idx = tid + i * 256;
        if (idx < 1024) {
            const int plane = idx >> 9;
            const int rem = idx & 511;
            const int row = rem >> 2, c4 = rem & 3;
            const __nv_bfloat16* src =
                (plane ? gAl : gAh) + (size_t)row * lda + k0 + c4 * 8;
            const unsigned dst = base + plane * A_PLANE_B + row * 80 + c4 * 16;
            asm volatile("cp.async.cg.shared.global [%0], [%1], 16;"
                         :: "r"(dst), "l"(src));
        } else {
            const int idx2 = idx - 1024;
            const int plane = idx2 >> 8;
            const int rem = idx2 & 255;
            const int row = rem >> 2, c4 = rem & 3;
            const __nv_bfloat16* src =
                (plane ? gBl : gBh) + (size_t)row * ldb + k0 + c4 * 8;
            const unsigned dst = base + B_SECT + plane * B_PLANE_B + row * 80 + c4 * 16;
            asm volatile("cp.async.cg.shared.global [%0], [%1], 16;"
                         :: "r"(dst), "l"(src));
        }
    }
    asm volatile("cp.async.commit_group;");
}

__device__ __forceinline__ void gemm_core(
    unsigned sbase,
    const __nv_bfloat16* __restrict__ Ah, const __nv_bfloat16* __restrict__ Al,
    const __nv_bfloat16* __restrict__ Bh, const __nv_bfloat16* __restrict__ Bl,
    const float* __restrict__ bias, float* __restrict__ C,
    __nv_bfloat16* __restrict__ Ch, __nv_bfloat16* __restrict__ Cl,
    int K, int lda, int ldb, int ldc, float alpha, int mode,
    int m0, int n0)
{
    const int tid  = threadIdx.x;
    const int lane = tid & 31;
    const int wid  = tid >> 5;
    const int wm   = (wid >> 1) * 32;
    const int wn   = (wid & 1) * 32;
    const int g    = lane >> 2;
    const int t    = lane & 3;
    const int sub    = lane >> 3;
    const int subrow = lane & 7;
    const int a_off = ((sub & 1) * 8 + subrow) * SWW + (sub >> 1) * 4;
    const int b_off = ((sub >> 1) * 8 + subrow) * SWW + (sub & 1) * 4;

    const __nv_bfloat16* gAh = Ah + (size_t)m0 * lda;
    const __nv_bfloat16* gAl = Al + (size_t)m0 * lda;
    const __nv_bfloat16* gBh = Bh + (size_t)n0 * ldb;
    const __nv_bfloat16* gBl = Bl + (size_t)n0 * ldb;

    float acc[2][4][4];
#pragma unroll
    for (int mt = 0; mt < 2; mt++)
#pragma unroll
        for (int nt = 0; nt < 4; nt++)
#pragma unroll
            for (int e = 0; e < 4; e++) acc[mt][nt][e] = 0.0f;

    const int T = K / BK;
    stage_tile(sbase, 0, 0, tid, gAh, gAl, gBh, gBl, lda, ldb);

    for (int tt = 0; tt < T; tt++) {
        if (tt + 1 < T) {
            stage_tile(sbase, (tt + 1) & 1, (tt + 1) * BK, tid,
                       gAh, gAl, gBh, gBl, lda, ldb);
            asm volatile("cp.async.wait_group 1;");
        } else {
            asm volatile("cp.async.wait_group 0;");
        }
        __syncthreads();

        const unsigned base = sbase + (tt & 1) * BUF_B;
#pragma unroll
        for (int ks = 0; ks < 2; ks++) {
            unsigned ah[2][4], al[2][4], bh[4][2], bl[4][2];
#pragma unroll
            for (int mt = 0; mt < 2; mt++) {
                const unsigned ad = base + ((wm + mt * 16) * SWW + ks * 8 + a_off) * 4;
                LDSM4(ah[mt][0], ah[mt][1], ah[mt][2], ah[mt][3], ad);
                LDSM4(al[mt][0], al[mt][1], al[mt][2], al[mt][3], ad + A_PLANE_B);
            }
#pragma unroll
            for (int np = 0; np < 2; np++) {
                const unsigned bd = base + B_SECT +
                                    ((wn + np * 16) * SWW + ks * 8 + b_off) * 4;
                unsigned r0, r1, r2, r3;
                LDSM4(r0, r1, r2, r3, bd);
                bh[2*np][0] = r0; bh[2*np][1] = r1;
                bh[2*np+1][0] = r2; bh[2*np+1][1] = r3;
                LDSM4(r0, r1, r2, r3, bd + B_PLANE_B);
                bl[2*np][0] = r0; bl[2*np][1] = r1;
                bl[2*np+1][0] = r2; bl[2*np+1][1] = r3;
            }
#pragma unroll
            for (int mt = 0; mt < 2; mt++)
#pragma unroll
                for (int nt = 0; nt < 4; nt++) {
                    mma_bf16(acc[mt][nt], al[mt], bh[nt]);
                    mma_bf16(acc[mt][nt], ah[mt], bl[nt]);
                    mma_bf16(acc[mt][nt], ah[mt], bh[nt]);
                }
        }
        __syncthreads();
    }

    // ---- epilogue ----
#pragma unroll
    for (int mt = 0; mt < 2; mt++) {
        const int rowA = m0 + wm + mt * 16 + g;
        const int rowB = rowA + 8;
#pragma unroll
        for (int nt = 0; nt < 4; nt++) {
            const int col = n0 + wn + nt * 8 + 2 * t;
            float bx = 0.0f, by = 0.0f;
            if (bias) { bx = bias[col]; by = bias[col + 1]; }
            float lox = acc[mt][nt][0] * alpha + bx;
            float loy = acc[mt][nt][1] * alpha + by;
            float hix = acc[mt][nt][2] * alpha + bx;
            float hiy = acc[mt][nt][3] * alpha + by;
            if (mode == 0) {
                *(float2*)&C[(size_t)rowA * ldc + col] = make_float2(lox, loy);
                *(float2*)&C[(size_t)rowB * ldc + col] = make_float2(hix, hiy);
            } else if (mode == 1) {
                const int h = col >> 6, tc = col & 63;
                *(float2*)&C[((size_t)h * SQ + rowA) * HD + tc] = make_float2(lox, loy);
                *(float2*)&C[((size_t)h * SQ + rowB) * HD + tc] = make_float2(hix, hiy);
            } else {
                const int h = col >> 6, tc = col & 63;
                __nv_bfloat16 h0,h1,h2,h3,l0,l1,l2,l3;
                bsplit(lox, h0, l0); bsplit(loy, h1, l1);
                bsplit(hix, h2, l2); bsplit(hiy, h3, l3);
                *(__nv_bfloat162*)&Ch[((size_t)h * SQ + rowA) * HD + tc] = __nv_bfloat162(h0, h1);
                *(__nv_bfloat162*)&Cl[((size_t)h * SQ + rowA) * HD + tc] = __nv_bfloat162(l0, l1);
                *(__nv_bfloat162*)&Ch[((size_t)h * SQ + rowB) * HD + tc] = __nv_bfloat162(h2, h3);
                *(__nv_bfloat162*)&Cl[((size_t)h * SQ + rowB) * HD + tc] = __nv_bfloat162(l2, l3);
            }
        }
    }
}

// ---- generic z-batched wrapper (scores, out-proj) ----
__global__ __launch_bounds__(256, 2) void nt_bf16x3_gemm(
    const __nv_bfloat16* __restrict__ Ah, const __nv_bfloat16* __restrict__ Al,
    const __nv_bfloat16* __restrict__ Bh, const __nv_bfloat16* __restrict__ Bl,
    const float* __restrict__ bias, float* __restrict__ C,
    int K, int lda, int ldb, int ldc, float alpha,
    long strA, long strB, long strC)
{
    extern __shared__ unsigned sm[];
    unsigned sbase = (unsigned)__cvta_generic_to_shared(sm);
    gemm_core(sbase,
              Ah + (size_t)blockIdx.z * strA, Al + (size_t)blockIdx.z * strA,
              Bh + (size_t)blockIdx.z * strB, Bl + (size_t)blockIdx.z * strB,
              bias, C + (size_t)blockIdx.z * strC, nullptr, nullptr,
              K, lda, ldb, ldc, alpha, 0,
              blockIdx.y * 128, blockIdx.x * 64);
}

// ---- fused QKV projection: blockIdx.z selects Q/K/V ----
__global__ __launch_bounds__(256, 2) void qkv_gemm(
    const float* __restrict__ bq, const float* __restrict__ bk,
    const float* __restrict__ bv)
{
    extern __shared__ unsigned sm[];
    unsigned sbase = (unsigned)__cvta_generic_to_shared(sm);
    const int z = blockIdx.z;
    const size_t DD = (size_t)DIM * DIM;
    const float* bias = (z == 0) ? bq : (z == 1) ? bk : bv;
    float* C = (z == 2) ? g_V : nullptr;
    __nv_bfloat16* Ch = (z == 0) ? g_Qh : (z == 1) ? g_Kh : nullptr;
    __nv_bfloat16* Cl = (z == 0) ? g_Ql : (z == 1) ? g_Kl : nullptr;
    gemm_core(sbase, g_xh, g_xl, g_WTh + z * DD, g_WTl + z * DD,
              bias, C, Ch, Cl,
              DIM, DIM, DIM, DIM, 1.0f, (z == 2) ? 1 : 2,
              blockIdx.y * 128, blockIdx.x * 64);
}

// ============================================================
// V column sums: stage A (64 partial blocks) + stage B (reduce)
// ============================================================
__global__ __launch_bounds__(256) void vsum_part()
{
    const int h  = blockIdx.x >> 2;
    const int qd = blockIdx.x & 3;
    const int t = threadIdx.x & 63;
    const int g = threadIdx.x >> 6;
    const float* Vh = g_V + (size_t)h * SQ * HD + (size_t)(qd * 512 + g * 128) * HD;
    float s = 0.0f;
    for (int r = 0; r < 128; ++r)
        s += Vh[(size_t)r * HD + t];
    __shared__ float red[4][64];
    red[g][t] = s;
    __syncthreads();
    if (g == 0)
        g_vsum_part[blockIdx.x][t] = red[0][t] + red[1][t] + red[2][t] + red[3][t];
}

__global__ __launch_bounds__(256) void vsum_reduce()
{
    const int i = blockIdx.x * 256 + threadIdx.x;   // 0..1023
    const int h = i >> 6, t = i & 63;
    g_vsum[i] = g_vsum_part[h * 4 + 0][t] + g_vsum_part[h * 4 + 1][t]
              + g_vsum_part[h * 4 + 2][t] + g_vsum_part[h * 4 + 3][t];
}

// ============================================================
// Top-16 (exact fp32, threshold-pruned) + sparse softmax +
// V gather. One warp per (h, q). Output -> bf16 hi/lo planes.
//
// tau = 16th largest of the 32 per-lane maxima. The top-16 lane
// maxima are 16 distinct elements >= tau, so every global top-16
// element has value >= tau: pruning below tau is exact. Survivors
// (exp. ~22) are ballot-compacted to smem; selection runs 16
// argmax rounds with (value desc, index asc) tiebreak == jax
// top_k first-occurrence semantics. cnt > 64 (mass ties) falls
// back to the old exact insertion path.
// ============================================================
__global__ __launch_bounds__(128) void topk_attend()
{
    const unsigned FULL = 0xffffffffu;
    const int wslot = threadIdx.x >> 5;
    const int gwarp = (blockIdx.x * 128 + threadIdx.x) >> 5;
    const int lane  = threadIdx.x & 31;
    const int h = gwarp >> 11;
    const int q = gwarp & 2047;

    __shared__ float sval[4][64];
    __shared__ int   sidx[4][64];

    const float* row = g_scores + ((size_t)h * SQ + q) * SQ;

    // ---- pass 1: per-lane max over 64 strided elements ----
    float mx = -1e30f;
#pragma unroll
    for (int c = 0; c < 16; c++) {
        float4 v = *(const float4*)&row[c * 128 + lane * 4];
        mx = fmaxf(mx, fmaxf(fmaxf(v.x, v.y), fmaxf(v.z, v.w)));
    }
    // bitonic ascending sort of the 32 lane maxima
    float sv = mx;
#pragma unroll
    for (int k = 2; k <= 32; k <<= 1) {
#pragma unroll
        for (int j = k >> 1; j > 0; j >>= 1) {
            float o = __shfl_xor_sync(FULL, sv, j);
            bool keepMin = (((lane & k) == 0) == ((lane & j) == 0));
            sv = keepMin ? fminf(sv, o) : fmaxf(sv, o);
        }
    }
    const float tau = __shfl_sync(FULL, sv, 16);  // 16th largest lane max

    // ---- pass 2: ballot-compact survivors (val >= tau) ----
    int cnt = 0;
#pragma unroll
    for (int c = 0; c < 16; c++) {
        const int base = c * 128 + lane * 4;
        float4 v = *(const float4*)&row[base];
        float vals[4] = {v.x, v.y, v.z, v.w};
#pragma unroll
        for (int j = 0; j < 4; j++) {
            bool p = (vals[j] >= tau);
            unsigned mk = __ballot_sync(FULL, p);
            if (p) {
                int pos = cnt + __popc(mk & ((1u << lane) - 1u));
                if (pos < 64) { sval[wslot][pos] = vals[j]; sidx[wslot][pos] = base + j; }
            }
            cnt += __popc(mk);
        }
    }
    __syncwarp();

    float fv = -1e30f;
    int   fi = 0;

    if (cnt <= 64) {
        // ---- selection from <=64 candidates (2 regs/lane) ----
        float c0 = -1e30f, c1 = -1e30f;
        int   i0 = 0x7fffffff, i1 = 0x7fffffff;
        if (lane < cnt)      { c0 = sval[wslot][lane];      i0 = sidx[wslot][lane]; }
        if (lane + 32 < cnt) { c1 = sval[wslot][lane + 32]; i1 = sidx[wslot][lane + 32]; }
        for (int r = 0; r < 16; r++) {
            bool first = (c0 > c1) || (c0 == c1 && i0 < i1);
            float bv = first ? c0 : c1;
            int   bi = first ? i0 : i1;
            int   bl = lane * 2 + (first ? 0 : 1);
#pragma unroll
            for (int off = 16; off > 0; off >>= 1) {
                float ov = __shfl_down_sync(FULL, bv, off);
                int   oi = __shfl_down_sync(FULL, bi, off);
                int   ol = __shfl_down_sync(FULL, bl, off);
                if (ov > bv || (ov == bv && oi < bi)) { bv = ov; bi = oi; bl = ol; }
            }
            bv = __shfl_sync(FULL, bv, 0);
            bi = __shfl_sync(FULL, bi, 0);
            bl = __shfl_sync(FULL, bl, 0);
            if (lane == (bl >> 1)) {
                if ((bl & 1) == 0) { c0 = -1e30f; i0 = 0x7fffffff; }
                else               { c1 = -1e30f; i1 = 0x7fffffff; }
            }
            if (lane == r) { fv = bv; fi = bi; }
        }
    } else {
        // ---- rare exact fallback: per-lane sorted top-16 + merge ----
        float lv[16];
        int   li[16];
#pragma unroll
        for (int i = 0; i < 16; i++) { lv[i] = -1e30f; li[i] = 0; }
#pragma unroll 4
        for (int c = 0; c < 16; c++) {
            const int base = c * 128 + lane * 4;
            float4 v4 = *(const float4*)&row[base];
            float vals[4] = {v4.x, v4.y, v4.z, v4.w};
#pragma unroll
            for (int j = 0; j < 4; j++) {
                const float val = vals[j];
                if (val > lv[15]) {
                    lv[15] = val; li[15] = base + j;
#pragma unroll
                    for (int p = 15; p >= 1; --p) {
                        if (lv[p] > lv[p - 1]) {
                            float tv = lv[p]; lv[p] = lv[p - 1]; lv[p - 1] = tv;
                            int   ti = li[p]; li[p] = li[p - 1]; li[p - 1] = ti;
                        }
                    }
                }
            }
        }
        for (int r = 0; r < 16; r++) {
            float bv = lv[0]; int bi = li[0]; int bl = lane;
#pragma unroll
            for (int off = 16; off > 0; off >>= 1) {
                float ov = __shfl_down_sync(FULL, bv, off);
                int   oi = __shfl_down_sync(FULL, bi, off);
                int   ol = __shfl_down_sync(FULL, bl, off);
                if (ov > bv || (ov == bv && oi < bi)) { bv = ov; bi = oi; bl = ol; }
            }
            bv = __shfl_sync(FULL, bv, 0);
            bi = __shfl_sync(FULL, bi, 0);
            bl = __shfl_sync(FULL, bl, 0);
            if (lane == bl && li[0] == bi) {
#pragma unroll
                for (int p = 0; p < 15; p++) { lv[p] = lv[p + 1]; li[p] = li[p + 1]; }
                lv[15] = -1e30f;
            }
            if (lane == r) { fv = bv; fi = bi; }
        }
    }

    // ---- sparse softmax (zeros participate) ----
    float m = __shfl_sync(FULL, fv, 0);
    m = fmaxf(m, 0.0f);
    float e = (lane < 16) ? expf(fv - m) : 0.0f;
    float z = e;
#pragma unroll
    for (int off = 16; off > 0; off >>= 1)
        z += __shfl_xor_sync(FULL, z, off);
    const float e0 = expf(-m);
    const float Z  = z + (float)(SQ - FACT) * e0;
    const float p0 = e0 / Z;
    const float w  = e / Z - p0;

    // ---- gather 16 V rows + p0 * vsum ----
    const float* Vh = g_V + (size_t)h * SQ * HD;
    float acc0 = p0 * g_vsum[h * HD + lane];
    float acc1 = p0 * g_vsum[h * HD + lane + 32];
#pragma unroll
    for (int i = 0; i < 16; i++) {
        const float wi  = __shfl_sync(FULL, w,  i);
        const int   idx = __shfl_sync(FULL, fi, i);
        const float* vr = Vh + (size_t)idx * HD;
        acc0 = fmaf(wi, vr[lane],      acc0);
        acc1 = fmaf(wi, vr[lane + 32], acc1);
    }
    // write output directly as bf16 hi/lo planes (layout [s][d])
    const size_t o = (size_t)q * DIM + h * HD;
    __nv_bfloat16 h0, l0, h1, l1;
    bsplit(acc0, h0, l0);
    bsplit(acc1, h1, l1);
    g_ath[o + lane]      = h0;
    g_atl[o + lane]      = l0;
    g_ath[o + lane + 32] = h1;
    g_atl[o + lane + 32] = l1;
}

// ============================================================
extern "C" void kernel_launch(void* const* d_in, const int* in_sizes, int n_in,
                              void* d_out, int out_size)
{
    const float* x  = (const float*)d_in[0];
    const float* Wq = (const float*)d_in[1];
    const float* bq = (const float*)d_in[2];
    const float* Wk = (const float*)d_in[3];
    const float* bk = (const float*)d_in[4];
    const float* Wv = (const float*)d_in[5];
    const float* bv = (const float*)d_in[6];
    const float* Wo = (const float*)d_in[7];
    const float* bo = (const float*)d_in[8];
    float* out = (float*)d_out;

    float* scoresp;
    __nv_bfloat16 *xh, *xl, *ath, *atl, *WTh, *WTl, *Qh, *Ql, *Kh, *Kl;
    cudaGetSymbolAddress((void**)&scoresp, g_scores);
    cudaGetSymbolAddress((void**)&xh,  g_xh);  cudaGetSymbolAddress((void**)&xl,  g_xl);
    cudaGetSymbolAddress((void**)&ath, g_ath); cudaGetSymbolAddress((void**)&atl, g_atl);
    cudaGetSymbolAddress((void**)&WTh, g_WTh); cudaGetSymbolAddress((void**)&WTl, g_WTl);
    cudaGetSymbolAddress((void**)&Qh,  g_Qh);  cudaGetSymbolAddress((void**)&Ql,  g_Ql);
    cudaGetSymbolAddress((void**)&Kh,  g_Kh);  cudaGetSymbolAddress((void**)&Kl,  g_Kl);

    static int smem_set = 0;
    if (!smem_set) {
        cudaFuncSetAttribute(nt_bf16x3_gemm,
                             cudaFuncAttributeMaxDynamicSharedMemorySize, GSMEM_BYTES);
        cudaFuncSetAttribute(qkv_gemm,
                             cudaFuncAttributeMaxDynamicSharedMemorySize, GSMEM_BYTES);
        smem_set = 1;
    }

    const size_t DD = (size_t)DIM * DIM;

    // fused weight transposes + splits
    dim3 gT(DIM / 32, DIM / 32, 4);
    dim3 bT(32, 8);
    transpose_split4<<<gT, bT>>>(Wq, Wk, Wv, Wo, WTh, WTl);

    split_convert<<<(SQ * DIM / 4 + 255) / 256, 256>>>(x, xh, xl, SQ * DIM / 4);

    // fused Q/K/V projections
    dim3 gQKV(DIM / 64, SQ / 128, 3);
    qkv_gemm<<<gQKV, 256, GSMEM_BYTES>>>(bq, bk, bv);

    vsum_part<<<64, 256>>>();
    vsum_reduce<<<4, 256>>>();

    // scores: per-head NT GEMM -> fp32 (exact ranking + softmax values)
    dim3 gSc(SQ / 64, SQ / 128, NH);
    nt_bf16x3_gemm<<<gSc, 256, GSMEM_BYTES>>>(
        Qh, Ql, Kh, Kl, nullptr, scoresp,
        HD, HD, HD, SQ, 0.125f,
        (long)SQ * HD, (long)SQ * HD, (long)SQ * SQ);

    topk_attend<<<(NH * SQ) / 4, 128>>>();

    // output projection (reads bf16 planes written by topk)
    dim3 gO(DIM / 64, SQ / 128, 1);
    nt_bf16x3_gemm<<<gO, 256, GSMEM_BYTES>>>(
        ath, atl, WTh + 3 * DD, WTl + 3 * DD, bo, out,
        DIM, DIM, DIM, DIM, 1.0f, 0, 0, 0);
}

// round 15
// speedup vs baseline: 1.8490x; 1.0476x over previous
#include <cuda_runtime.h>
#include <cuda_bf16.h>
#include <math.h>

#define SQ   2048
#define DIM  1024
#define NH   16
#define HD   64
#define FACT 16

// ---- scratch (device globals: the sanctioned no-alloc scratch path) ----
__device__ float g_V[NH * SQ * HD];              // 8 MB fp32 [h][s][hd]
__device__ float g_scores[(size_t)NH * SQ * SQ]; // 256 MB fp32 [h][q][k]
__device__ float g_vsum[NH * HD];
__device__ float g_vsum_part[64][HD];

// bf16 split planes
__device__ __nv_bfloat16 g_xh[SQ * DIM],  g_xl[SQ * DIM];
__device__ __nv_bfloat16 g_ath[SQ * DIM], g_atl[SQ * DIM];   // attn out planes
__device__ __nv_bfloat16 g_WTh[4 * DIM * DIM], g_WTl[4 * DIM * DIM];
__device__ __nv_bfloat16 g_Qh[NH * SQ * HD], g_Ql[NH * SQ * HD];
__device__ __nv_bfloat16 g_Kh[NH * SQ * HD], g_Kl[NH * SQ * HD];

// ============================================================
// helpers
// ============================================================
__device__ __forceinline__ void bsplit(float v, __nv_bfloat16& h, __nv_bfloat16& l) {
    h = __float2bfloat16(v);
    l = __float2bfloat16(v - __bfloat162float(h));
}

__device__ __forceinline__ void mma_bf16(float* c, const unsigned* a, const unsigned* b) {
    asm volatile(
        "mma.sync.aligned.m16n8k16.row.col.f32.bf16.bf16.f32 "
        "{%0,%1,%2,%3}, {%4,%5,%6,%7}, {%8,%9}, {%0,%1,%2,%3};"
        : "+f"(c[0]), "+f"(c[1]), "+f"(c[2]), "+f"(c[3])
        : "r"(a[0]), "r"(a[1]), "r"(a[2]), "r"(a[3]),
          "r"(b[0]), "r"(b[1]));
}

#define LDSM4(R0, R1, R2, R3, A)                                          \
    asm volatile("ldmatrix.sync.aligned.m8n8.x4.shared.b16 "              \
                 "{%0,%1,%2,%3}, [%4];"                                   \
                 : "=r"(R0), "=r"(R1), "=r"(R2), "=r"(R3) : "r"(A))

// ============================================================
// fused 4x 1024x1024 transpose + bf16 hi/lo split (z = which W)
// ============================================================
__global__ __launch_bounds__(256) void transpose_split4(
    const float* __restrict__ W0, const float* __restrict__ W1,
    const float* __restrict__ W2, const float* __restrict__ W3,
    __nv_bfloat16* __restrict__ Dh, __nv_bfloat16* __restrict__ Dl)
{
    __shared__ float tile[32][33];
    const int z = blockIdx.z;
    const float* S = (z == 0) ? W0 : (z == 1) ? W1 : (z == 2) ? W2 : W3;
    const size_t off = (size_t)z * DIM * DIM;
    int x = blockIdx.x * 32 + threadIdx.x;
    int y = blockIdx.y * 32 + threadIdx.y;
#pragma unroll
    for (int j = 0; j < 32; j += 8)
        tile[threadIdx.y + j][threadIdx.x] = S[(size_t)(y + j) * DIM + x];
    __syncthreads();
    x = blockIdx.y * 32 + threadIdx.x;
    y = blockIdx.x * 32 + threadIdx.y;
#pragma unroll
    for (int j = 0; j < 32; j += 8) {
        float v = tile[threadIdx.x][threadIdx.y + j];
        __nv_bfloat16 h, l;
        bsplit(v, h, l);
        Dh[off + (size_t)(y + j) * DIM + x] = h;
        Dl[off + (size_t)(y + j) * DIM + x] = l;
    }
}

// ============================================================
// elementwise fp32 -> bf16 hi/lo split (x only)
// ============================================================
__global__ __launch_bounds__(256) void split_convert(
    const float* __restrict__ S,
    __nv_bfloat16* __restrict__ Dh, __nv_bfloat16* __restrict__ Dl, int n4)
{
    int i = blockIdx.x * 256 + threadIdx.x;
    if (i >= n4) return;
    float4 v = *(const float4*)&S[i * 4];
    __nv_bfloat16 h0,h1,h2,h3,l0,l1,l2,l3;
    bsplit(v.x, h0, l0); bsplit(v.y, h1, l1);
    bsplit(v.z, h2, l2); bsplit(v.w, h3, l3);
    __nv_bfloat162* ph = (__nv_bfloat162*)&Dh[i * 4];
    __nv_bfloat162* pl = (__nv_bfloat162*)&Dl[i * 4];
    ph[0] = __nv_bfloat162(h0, h1); ph[1] = __nv_bfloat162(h2, h3);
    pl[0] = __nv_bfloat162(l0, l1); pl[1] = __nv_bfloat162(l2, l3);
}

// ============================================================
// bf16x3 GEMM core. Tile M128 x N128, BK=32, 8 warps of 64x32,
// ldmatrix fragments, cp.async double-buffered, 80KB smem ->
// 2 CTAs/SM.
// mode: 0 = fp32 C[row*ldc+col]; 1 = fp32 remap [h][row][t];
//       2 = bf16 split remap to Ch/Cl.
// ============================================================
#define BK        32
#define SWW       20                 // words per smem row (16 data + 4 pad)
#define PLANE_B   10240              // 128 rows * 80 B
#define B_SECT    20480              // 2 A planes
#define BUF_B     40960              // 4 planes per buffer
#define GSMEM_BYTES 81920

__device__ __forceinline__ void stage_tile(
    unsigned sbase, int buf, int k0, int tid,
    const __nv_bfloat16* gAh, const __nv_bfloat16* gAl,
    const __nv_bfloat16* gBh, const __nv_bfloat16* gBl,
    int lda, int ldb)
{
    const unsigned base = sbase + buf * BUF_B;
#pragma unroll
    for (int i = 0; i < 8; i++) {
        const int idx = tid + i * 256;         // 0..2047
        const int plane = idx >> 9;            // 0..3
        const int rem = idx & 511;
        const int row = rem >> 2, c4 = rem & 3;
        const __nv_bfloat16* pp =
            (plane == 0) ? gAh : (plane == 1) ? gAl : (plane == 2) ? gBh : gBl;
        const int ld = (plane < 2) ? lda : ldb;
        const __nv_bfloat16* src = pp + (size_t)row * ld + k0 + c4 * 8;
        const unsigned dst = base + plane * PLANE_B + row * 80 + c4 * 16;
        asm volatile("cp.async.cg.shared.global [%0], [%1], 16;"
                     :: "r"(dst), "l"(src));
    }
    asm volatile("cp.async.commit_group;");
}

__device__ __forceinline__ void gemm_core(
    unsigned sbase,
    const __nv_bfloat16* __restrict__ Ah, const __nv_bfloat16* __restrict__ Al,
    const __nv_bfloat16* __restrict__ Bh, const __nv_bfloat16* __restrict__ Bl,
    const float* __restrict__ bias, float* __restrict__ C,
    __nv_bfloat16* __restrict__ Ch, __nv_bfloat16* __restrict__ Cl,
    int K, int lda, int ldb, int ldc, float alpha, int mode,
    int m0, int n0)
{
    const int tid  = threadIdx.x;
    const int lane = tid & 31;
    const int wid  = tid >> 5;
    const int wm   = (wid >> 2) * 64;     // 0,64
    const int wn   = (wid & 3) * 32;      // 0,32,64,96
    const int g    = lane >> 2;
    const int t    = lane & 3;
    const int sub    = lane >> 3;
    const int subrow = lane & 7;
    const int a_off = ((sub & 1) * 8 + subrow) * SWW + (sub >> 1) * 4;
    const int b_off = ((sub >> 1) * 8 + subrow) * SWW + (sub & 1) * 4;

    const __nv_bfloat16* gAh = Ah + (size_t)m0 * lda;
    const __nv_bfloat16* gAl = Al + (size_t)m0 * lda;
    const __nv_bfloat16* gBh = Bh + (size_t)n0 * ldb;
    const __nv_bfloat16* gBl = Bl + (size_t)n0 * ldb;

    float acc[4][4][4];
#pragma unroll
    for (int mt = 0; mt < 4; mt++)
#pragma unroll
        for (int nt = 0; nt < 4; nt++)
#pragma unroll
            for (int e = 0; e < 4; e++) acc[mt][nt][e] = 0.0f;

    const int T = K / BK;
    stage_tile(sbase, 0, 0, tid, gAh, gAl, gBh, gBl, lda, ldb);

    for (int tt = 0; tt < T; tt++) {
        if (tt + 1 < T) {
            stage_tile(sbase, (tt + 1) & 1, (tt + 1) * BK, tid,
                       gAh, gAl, gBh, gBl, lda, ldb);
            asm volatile("cp.async.wait_group 1;");
        } else {
            asm volatile("cp.async.wait_group 0;");
        }
        __syncthreads();

        const unsigned base = sbase + (tt & 1) * BUF_B;
#pragma unroll
        for (int ks = 0; ks < 2; ks++) {
            unsigned ah[4][4], al[4][4], bh[4][2], bl[4][2];
#pragma unroll
            for (int mt = 0; mt < 4; mt++) {
                const unsigned ad = base + ((wm + mt * 16) * SWW + ks * 8 + a_off) * 4;
                LDSM4(ah[mt][0], ah[mt][1], ah[mt][2], ah[mt][3], ad);
                LDSM4(al[mt][0], al[mt][1], al[mt][2], al[mt][3], ad + PLANE_B);
            }
#pragma unroll
            for (int np = 0; np < 2; np++) {
                const unsigned bd = base + B_SECT +
                                    ((wn + np * 16) * SWW + ks * 8 + b_off) * 4;
                unsigned r0, r1, r2, r3;
                LDSM4(r0, r1, r2, r3, bd);
                bh[2*np][0] = r0; bh[2*np][1] = r1;
                bh[2*np+1][0] = r2; bh[2*np+1][1] = r3;
                LDSM4(r0, r1, r2, r3, bd + PLANE_B);
                bl[2*np][0] = r0; bl[2*np][1] = r1;
                bl[2*np+1][0] = r2; bl[2*np+1][1] = r3;
            }
#pragma unroll
            for (int mt = 0; mt < 4; mt++)
#pragma unroll
                for (int nt = 0; nt < 4; nt++) {
                    mma_bf16(acc[mt][nt], al[mt], bh[nt]);
                    mma_bf16(acc[mt][nt], ah[mt], bl[nt]);
                    mma_bf16(acc[mt][nt], ah[mt], bh[nt]);
                }
        }
        __syncthreads();
    }

    // ---- epilogue ----
#pragma unroll
    for (int mt = 0; mt < 4; mt++) {
        const int rowA = m0 + wm + mt * 16 + g;
        const int rowB = rowA + 8;
#pragma unroll
        for (int nt = 0; nt < 4; nt++) {
            const int col = n0 + wn + nt * 8 + 2 * t;
            float bx = 0.0f, by = 0.0f;
            if (bias) { bx = bias[col]; by = bias[col + 1]; }
            float lox = acc[mt][nt][0] * alpha + bx;
            float loy = acc[mt][nt][1] * alpha + by;
            float hix = acc[mt][nt][2] * alpha + bx;
            float hiy = acc[mt][nt][3] * alpha + by;
            if (mode == 0) {
                *(float2*)&C[(size_t)rowA * ldc + col] = make_float2(lox, loy);
                *(float2*)&C[(size_t)rowB * ldc + col] = make_float2(hix, hiy);
            } else if (mode == 1) {
                const int h = col >> 6, tc = col & 63;
                *(float2*)&C[((size_t)h * SQ + rowA) * HD + tc] = make_float2(lox, loy);
                *(float2*)&C[((size_t)h * SQ + rowB) * HD + tc] = make_float2(hix, hiy);
            } else {
                const int h = col >> 6, tc = col & 63;
                __nv_bfloat16 h0,h1,h2,h3,l0,l1,l2,l3;
                bsplit(lox, h0, l0); bsplit(loy, h1, l1);
                bsplit(hix, h2, l2); bsplit(hiy, h3, l3);
                *(__nv_bfloat162*)&Ch[((size_t)h * SQ + rowA) * HD + tc] = __nv_bfloat162(h0, h1);
                *(__nv_bfloat162*)&Cl[((size_t)h * SQ + rowA) * HD + tc] = __nv_bfloat162(l0, l1);
                *(__nv_bfloat162*)&Ch[((size_t)h * SQ + rowB) * HD + tc] = __nv_bfloat162(h2, h3);
                *(__nv_bfloat162*)&Cl[((size_t)h * SQ + rowB) * HD + tc] = __nv_bfloat162(l2, l3);
            }
        }
    }
}

// ---- generic z-batched wrapper (scores, out-proj) ----
__global__ __launch_bounds__(256, 2) void nt_bf16x3_gemm(
    const __nv_bfloat16* __restrict__ Ah, const __nv_bfloat16* __restrict__ Al,
    const __nv_bfloat16* __restrict__ Bh, const __nv_bfloat16* __restrict__ Bl,
    const float* __restrict__ bias, float* __restrict__ C,
    int K, int lda, int ldb, int ldc, float alpha,
    long strA, long strB, long strC)
{
    extern __shared__ unsigned sm[];
    unsigned sbase = (unsigned)__cvta_generic_to_shared(sm);
    gemm_core(sbase,
              Ah + (size_t)blockIdx.z * strA, Al + (size_t)blockIdx.z * strA,
              Bh + (size_t)blockIdx.z * strB, Bl + (size_t)blockIdx.z * strB,
              bias, C + (size_t)blockIdx.z * strC, nullptr, nullptr,
              K, lda, ldb, ldc, alpha, 0,
              blockIdx.y * 128, blockIdx.x * 128);
}

// ---- fused QKV projection: blockIdx.z selects Q/K/V ----
__global__ __launch_bounds__(256, 2) void qkv_gemm(
    const float* __restrict__ bq, const float* __restrict__ bk,
    const float* __restrict__ bv)
{
    extern __shared__ unsigned sm[];
    unsigned sbase = (unsigned)__cvta_generic_to_shared(sm);
    const int z = blockIdx.z;
    const size_t DD = (size_t)DIM * DIM;
    const float* bias = (z == 0) ? bq : (z == 1) ? bk : bv;
    float* C = (z == 2) ? g_V : nullptr;
    __nv_bfloat16* Ch = (z == 0) ? g_Qh : (z == 1) ? g_Kh : nullptr;
    __nv_bfloat16* Cl = (z == 0) ? g_Ql : (z == 1) ? g_Kl : nullptr;
    gemm_core(sbase, g_xh, g_xl, g_WTh + z * DD, g_WTl + z * DD,
              bias, C, Ch, Cl,
              DIM, DIM, DIM, DIM, 1.0f, (z == 2) ? 1 : 2,
              blockIdx.y * 128, blockIdx.x * 128);
}

// ============================================================
// V column sums: stage A (64 partial blocks) + stage B (reduce)
// ============================================================
__global__ __launch_bounds__(256) void vsum_part()
{
    const int h  = blockIdx.x >> 2;
    const int qd = blockIdx.x & 3;
    const int t = threadIdx.x & 63;
    const int g = threadIdx.x >> 6;
    const float* Vh = g_V + (size_t)h * SQ * HD + (size_t)(qd * 512 + g * 128) * HD;
    float s = 0.0f;
    for (int r = 0; r < 128; ++r)
        s += Vh[(size_t)r * HD + t];
    __shared__ float red[4][64];
    red[g][t] = s;
    __syncthreads();
    if (g == 0)
        g_vsum_part[blockIdx.x][t] = red[0][t] + red[1][t] + red[2][t] + red[3][t];
}

__global__ __launch_bounds__(256) void vsum_reduce()
{
    const int i = blockIdx.x * 256 + threadIdx.x;   // 0..1023
    const int h = i >> 6, t = i & 63;
    g_vsum[i] = g_vsum_part[h * 4 + 0][t] + g_vsum_part[h * 4 + 1][t]
              + g_vsum_part[h * 4 + 2][t] + g_vsum_part[h * 4 + 3][t];
}

// ============================================================
// Top-16 (exact fp32, threshold-pruned) + sparse softmax +
// V gather. One warp per (h, q). Output -> bf16 hi/lo planes.
// ============================================================
__global__ __launch_bounds__(128) void topk_attend()
{
    const unsigned FULL = 0xffffffffu;
    const int wslot = threadIdx.x >> 5;
    const int gwarp = (blockIdx.x * 128 + threadIdx.x) >> 5;
    const int lane  = threadIdx.x & 31;
    const int h = gwarp >> 11;
    const int q = gwarp & 2047;

    __shared__ float sval[4][64];
    __shared__ int   sidx[4][64];

    const float* row = g_scores + ((size_t)h * SQ + q) * SQ;

    // ---- pass 1: per-lane max over 64 strided elements ----
    float mx = -1e30f;
#pragma unroll
    for (int c = 0; c < 16; c++) {
        float4 v = *(const float4*)&row[c * 128 + lane * 4];
        mx = fmaxf(mx, fmaxf(fmaxf(v.x, v.y), fmaxf(v.z, v.w)));
    }
    float sv = mx;
#pragma unroll
    for (int k = 2; k <= 32; k <<= 1) {
#pragma unroll
        for (int j = k >> 1; j > 0; j >>= 1) {
            float o = __shfl_xor_sync(FULL, sv, j);
            bool keepMin = (((lane & k) == 0) == ((lane & j) == 0));
            sv = keepMin ? fminf(sv, o) : fmaxf(sv, o);
        }
    }
    const float tau = __shfl_sync(FULL, sv, 16);

    // ---- pass 2: ballot-compact survivors (val >= tau) ----
    int cnt = 0;
#pragma unroll
    for (int c = 0; c < 16; c++) {
        const int base = c * 128 + lane * 4;
        float4 v = *(const float4*)&row[base];
        float vals[4] = {v.x, v.y, v.z, v.w};
#pragma unroll
        for (int j = 0; j < 4; j++) {
            bool p = (vals[j] >= tau);
            unsigned mk = __ballot_sync(FULL, p);
            if (p) {
                int pos = cnt + __popc(mk & ((1u << lane) - 1u));
                if (pos < 64) { sval[wslot][pos] = vals[j]; sidx[wslot][pos] = base + j; }
            }
            cnt += __popc(mk);
        }
    }
    __syncwarp();

    float fv = -1e30f;
    int   fi = 0;

    if (cnt <= 64) {
        float c0 = -1e30f, c1 = -1e30f;
        int   i0 = 0x7fffffff, i1 = 0x7fffffff;
        if (lane < cnt)      { c0 = sval[wslot][lane];      i0 = sidx[wslot][lane]; }
        if (lane + 32 < cnt) { c1 = sval[wslot][lane + 32]; i1 = sidx[wslot][lane + 32]; }
        for (int r = 0; r < 16; r++) {
            bool first = (c0 > c1) || (c0 == c1 && i0 < i1);
            float bv = first ? c0 : c1;
            int   bi = first ? i0 : i1;
            int   bl = lane * 2 + (first ? 0 : 1);
#pragma unroll
            for (int off = 16; off > 0; off >>= 1) {
                float ov = __shfl_down_sync(FULL, bv, off);
                int   oi = __shfl_down_sync(FULL, bi, off);
                int   ol = __shfl_down_sync(FULL, bl, off);
                if (ov > bv || (ov == bv && oi < bi)) { bv = ov; bi = oi; bl = ol; }
            }
            bv = __shfl_sync(FULL, bv, 0);
            bi = __shfl_sync(FULL, bi, 0);
            bl = __shfl_sync(FULL, bl, 0);
            if (lane == (bl >> 1)) {
                if ((bl & 1) == 0) { c0 = -1e30f; i0 = 0x7fffffff; }
                else               { c1 = -1e30f; i1 = 0x7fffffff; }
            }
            if (lane == r) { fv = bv; fi = bi; }
        }
    } else {
        float lv[16];
        int   li[16];
#pragma unroll
        for (int i = 0; i < 16; i++) { lv[i] = -1e30f; li[i] = 0; }
#pragma unroll 4
        for (int c = 0; c < 16; c++) {
            const int base = c * 128 + lane * 4;
            float4 v4 = *(const float4*)&row[base];
            float vals[4] = {v4.x, v4.y, v4.z, v4.w};
#pragma unroll
            for (int j = 0; j < 4; j++) {
                const float val = vals[j];
                if (val > lv[15]) {
                    lv[15] = val; li[15] = base + j;
#pragma unroll
                    for (int p = 15; p >= 1; --p) {
                        if (lv[p] > lv[p - 1]) {
                            float tv = lv[p]; lv[p] = lv[p - 1]; lv[p - 1] = tv;
                            int   ti = li[p]; li[p] = li[p - 1]; li[p - 1] = ti;
                        }
                    }
                }
            }
        }
        for (int r = 0; r < 16; r++) {
            float bv = lv[0]; int bi = li[0]; int bl = lane;
#pragma unroll
            for (int off = 16; off > 0; off >>= 1) {
                float ov = __shfl_down_sync(FULL, bv, off);
                int   oi = __shfl_down_sync(FULL, bi, off);
                int   ol = __shfl_down_sync(FULL, bl, off);
                if (ov > bv || (ov == bv && oi < bi)) { bv = ov; bi = oi; bl = ol; }
            }
            bv = __shfl_sync(FULL, bv, 0);
            bi = __shfl_sync(FULL, bi, 0);
            bl = __shfl_sync(FULL, bl, 0);
            if (lane == bl && li[0] == bi) {
#pragma unroll
                for (int p = 0; p < 15; p++) { lv[p] = lv[p + 1]; li[p] = li[p + 1]; }
                lv[15] = -1e30f;
            }
            if (lane == r) { fv = bv; fi = bi; }
        }
    }

    // ---- sparse softmax (zeros participate) ----
    float m = __shfl_sync(FULL, fv, 0);
    m = fmaxf(m, 0.0f);
    float e = (lane < 16) ? expf(fv - m) : 0.0f;
    float z = e;
#pragma unroll
    for (int off = 16; off > 0; off >>= 1)
        z += __shfl_xor_sync(FULL, z, off);
    const float e0 = expf(-m);
    const float Z  = z + (float)(SQ - FACT) * e0;
    const float p0 = e0 / Z;
    const float w  = e / Z - p0;

    // ---- gather 16 V rows + p0 * vsum ----
    const float* Vh = g_V + (size_t)h * SQ * HD;
    float acc0 = p0 * g_vsum[h * HD + lane];
    float acc1 = p0 * g_vsum[h * HD + lane + 32];
#pragma unroll
    for (int i = 0; i < 16; i++) {
        const float wi  = __shfl_sync(FULL, w,  i);
        const int   idx = __shfl_sync(FULL, fi, i);
        const float* vr = Vh + (size_t)idx * HD;
        acc0 = fmaf(wi, vr[lane],      acc0);
        acc1 = fmaf(wi, vr[lane + 32], acc1);
    }
    const size_t o = (size_t)q * DIM + h * HD;
    __nv_bfloat16 h0, l0, h1, l1;
    bsplit(acc0, h0, l0);
    bsplit(acc1, h1, l1);
    g_ath[o + lane]      = h0;
    g_atl[o + lane]      = l0;
    g_ath[o + lane + 32] = h1;
    g_atl[o + lane + 32] = l1;
}

// ============================================================
extern "C" void kernel_launch(void* const* d_in, const int* in_sizes, int n_in,
                              void* d_out, int out_size)
{
    const float* x  = (const float*)d_in[0];
    const float* Wq = (const float*)d_in[1];
    const float* bq = (const float*)d_in[2];
    const float* Wk = (const float*)d_in[3];
    const float* bk = (const float*)d_in[4];
    const float* Wv = (const float*)d_in[5];
    const float* bv = (const float*)d_in[6];
    const float* Wo = (const float*)d_in[7];
    const float* bo = (const float*)d_in[8];
    float* out = (float*)d_out;

    float* scoresp;
    __nv_bfloat16 *xh, *xl, *ath, *atl, *WTh, *WTl, *Qh, *Ql, *Kh, *Kl;
    cudaGetSymbolAddress((void**)&scoresp, g_scores);
    cudaGetSymbolAddress((void**)&xh,  g_xh);  cudaGetSymbolAddress((void**)&xl,  g_xl);
    cudaGetSymbolAddress((void**)&ath, g_ath); cudaGetSymbolAddress((void**)&atl, g_atl);
    cudaGetSymbolAddress((void**)&WTh, g_WTh); cudaGetSymbolAddress((void**)&WTl, g_WTl);
    cudaGetSymbolAddress((void**)&Qh,  g_Qh);  cudaGetSymbolAddress((void**)&Ql,  g_Ql);
    cudaGetSymbolAddress((void**)&Kh,  g_Kh);  cudaGetSymbolAddress((void**)&Kl,  g_Kl);

    static int smem_set = 0;
    if (!smem_set) {
        cudaFuncSetAttribute(nt_bf16x3_gemm,
                             cudaFuncAttributeMaxDynamicSharedMemorySize, GSMEM_BYTES);
        cudaFuncSetAttribute(qkv_gemm,
                             cudaFuncAttributeMaxDynamicSharedMemorySize, GSMEM_BYTES);
        smem_set = 1;
    }

    const size_t DD = (size_t)DIM * DIM;

    // fused weight transposes + splits
    dim3 gT(DIM / 32, DIM / 32, 4);
    dim3 bT(32, 8);
    transpose_split4<<<gT, bT>>>(Wq, Wk, Wv, Wo, WTh, WTl);

    split_convert<<<(SQ * DIM / 4 + 255) / 256, 256>>>(x, xh, xl, SQ * DIM / 4);

    // fused Q/K/V projections (128x128 tiles)
    dim3 gQKV(DIM / 128, SQ / 128, 3);   // (8, 16, 3)
    qkv_gemm<<<gQKV, 256, GSMEM_BYTES>>>(bq, bk, bv);

    vsum_part<<<64, 256>>>();
    vsum_reduce<<<4, 256>>>();

    // scores: per-head NT GEMM -> fp32 (exact ranking + softmax values)
    dim3 gSc(SQ / 128, SQ / 128, NH);    // (16, 16, 16)
    nt_bf16x3_gemm<<<gSc, 256, GSMEM_BYTES>>>(
        Qh, Ql, Kh, Kl, nullptr, scoresp,
        HD, HD, HD, SQ, 0.125f,
        (long)SQ * HD, (long)SQ * HD, (long)SQ * SQ);

    topk_attend<<<(NH * SQ) / 4, 128>>>();

    // output projection (reads bf16 planes written by topk)
    dim3 gO(DIM / 128, SQ / 128, 1);     // (8, 16, 1)
    nt_bf16x3_gemm<<<gO, 256, GSMEM_BYTES>>>(
        ath, atl, WTh + 3 * DD, WTl + 3 * DD, bo, out,
        DIM, DIM, DIM, DIM, 1.0f, 0, 0, 0);
}